// round 10
// baseline (speedup 1.0000x reference)
#include <cuda_runtime.h>
#include <cuda_bf16.h>
#include <math.h>
#include <stdint.h>

// ---------------- problem dims ------------------------------------------------
#define NB 1024
#define NT 64
#define ND 256
#define NL 256
#define NH 1024
#define EPSV 1e-7f
#define LOG2PI 1.8378770664093453f
#define BETAV (1.0f/3.0f)

typedef __nv_bfloat16 bf16;

// ---------------- scratch (device globals) ------------------------------------
__device__ __align__(16) bf16  g_y1[(size_t)NB * NT * NH];
__device__ __align__(16) bf16  g_ctx[(size_t)NB * NT * 512];
__device__ __align__(16) bf16  g_xst[(size_t)NB * NT * ND];
__device__ __align__(16) bf16  g_zs[(size_t)NB * NT * NL];
__device__ __align__(16) float g_z[NB * NL];
__device__ __align__(16) bf16  g_hf[NB * NH];
__device__ __align__(16) bf16  g_hh[NB * NH];
__device__ __align__(16) float g_q[NB * 512];
__device__ __align__(16) bf16  g_fctx[(size_t)NT * NB * NH];   // [t][b][1024] bf16
__device__ __align__(16) bf16  g_wtb[2424832];
__device__ float g_dkl8[8 * NB];
__device__ float g_kl0[NB];
__device__ float g_diffv[NL];
__device__ float g_partials[4096];
__device__ unsigned g_barct;

// weight offsets in g_wtb (elements), stored transposed [N][K]
#define W_ENC1 0
#define W_ENC2 262144
#define W_QZ0  524288
#define W_F1Z  786432      // f_w1 rows 0..255   -> [1024][256]
#define W_F1C  1048576     // f_w1 rows 256..767 -> [1024][512]
#define W_F2   1572864
#define W_H1   1835008
#define W_H2   2097152
#define W_PROJ 2359296

// ---------------- helpers -----------------------------------------------------
__device__ __forceinline__ uint32_t s2u(const void* p) {
    uint32_t a;
    asm("{ .reg .u64 t; cvta.to.shared.u64 t, %1; cvt.u32.u64 %0, t; }" : "=r"(a) : "l"(p));
    return a;
}
__device__ __forceinline__ void cp16(uint32_t saddr, const void* g) {
    asm volatile("cp.async.cg.shared.global [%0], [%1], 16;" :: "r"(saddr), "l"(g));
}
__device__ __forceinline__ void mma_bf16(float* c, uint32_t a0, uint32_t a1, uint32_t a2, uint32_t a3,
                                         uint32_t b0, uint32_t b1) {
    asm volatile("mma.sync.aligned.m16n8k16.row.col.f32.bf16.bf16.f32 "
                 "{%0,%1,%2,%3},{%4,%5,%6,%7},{%8,%9},{%0,%1,%2,%3};"
                 : "+f"(c[0]), "+f"(c[1]), "+f"(c[2]), "+f"(c[3])
                 : "r"(a0), "r"(a1), "r"(a2), "r"(a3), "r"(b0), "r"(b1));
}
__device__ __forceinline__ float block_reduce_sum_256(float v, float* sh) {
    int tid = threadIdx.x;
    sh[tid] = v;
    __syncthreads();
    #pragma unroll
    for (int s = 128; s > 0; s >>= 1) {
        if (tid < s) sh[tid] += sh[tid + s];
        __syncthreads();
    }
    float r = sh[0];
    __syncthreads();
    return r;
}
// grid barrier: monotonic counter, release-arrive / tight acquire-spin
__device__ __forceinline__ void gbar(unsigned* ctr, unsigned tgt) {
    __syncthreads();
    if (threadIdx.x == 0) {
        asm volatile("red.release.gpu.add.u32 [%0], 1;" :: "l"(ctr) : "memory");
        unsigned v;
        do {
            asm volatile("ld.acquire.gpu.u32 %0, [%1];" : "=r"(v) : "l"(ctr) : "memory");
        } while (v < tgt);
    }
    __syncthreads();
}

// ---------------- standalone bf16 GEMM (encoder / q / fctx / decoder) ---------
struct GArgs {
    const bf16* A; int lda;
    const bf16* W;            // transposed [N][K], row stride = K
    const float* bias;
    void* C; int ldc;
    int K;
};

// STOREs: OUTBF=1 -> bf16 linear; EPI=1 -> fused NLL (no store);
// TSCAT=1 -> bf16 store scattered to [t][b][1024] (m = b*64+t)
template<int BMT, int ACT, int OUTBF, int EPI, int TSCAT>
__global__ void __launch_bounds__(256)
gemm_bf(GArgs g0, GArgs g1, int mSplit,
        const float* __restrict__ xs, const float* __restrict__ nstd_p,
        float* __restrict__ partials)
{
    extern __shared__ char smem[];
    constexpr int MT  = (BMT + 31) / 32;
    constexpr int ASZ = BMT * 72;
    constexpr int BSZ = 128 * 72;
    constexpr int STG = ASZ + BSZ;

    const int tid  = threadIdx.x;
    const int wid  = tid >> 5;
    const int lane = tid & 31;
    const int lr   = lane >> 2;
    const int lc   = lane & 3;

    const bool grp1 = ((int)blockIdx.y >= mSplit);
    const GArgs g = grp1 ? g1 : g0;
    const int bm = (grp1 ? ((int)blockIdx.y - mSplit) : (int)blockIdx.y) * BMT;
    const int bn = (int)blockIdx.x * 128;

    bf16* sm = (bf16*)smem;
    const uint32_t sbase = s2u(smem);
    const int warpM = (wid >> 2) * (BMT / 2);
    const int warpN = (wid & 3) * 32;

    auto loadtile = [&](int s, int c) {
        const int k0 = c << 6;
        uint32_t sA = sbase + (uint32_t)(s * STG) * 2u;
        uint32_t sB = sA + (uint32_t)ASZ * 2u;
        const bf16* Ag = g.A + (size_t)bm * g.lda + k0;
        #pragma unroll
        for (int i = 0; i < BMT / 32; i++) {
            int idx = tid + (i << 8);
            int m = idx >> 3, k8 = (idx & 7) << 3;
            cp16(sA + (uint32_t)(m * 72 + k8) * 2u, Ag + (size_t)m * g.lda + k8);
        }
        const bf16* Wg = g.W + (size_t)bn * g.K + k0;
        #pragma unroll
        for (int i = 0; i < 4; i++) {
            int idx = tid + (i << 8);
            int n = idx >> 3, k8 = (idx & 7) << 3;
            cp16(sB + (uint32_t)(n * 72 + k8) * 2u, Wg + (size_t)n * g.K + k8);
        }
        asm volatile("cp.async.commit_group;" ::: "memory");
    };

    float acc[MT][4][4];
    #pragma unroll
    for (int mt = 0; mt < MT; mt++)
        #pragma unroll
        for (int nt = 0; nt < 4; nt++)
            #pragma unroll
            for (int r = 0; r < 4; r++) acc[mt][nt][r] = 0.f;

    const int nch = g.K >> 6;
    loadtile(0, 0);
    if (nch > 1) loadtile(1, 1);

    for (int c = 0; c < nch; c++) {
        if (c + 1 < nch) asm volatile("cp.async.wait_group 1;" ::: "memory");
        else             asm volatile("cp.async.wait_group 0;" ::: "memory");
        __syncthreads();
        const bf16* As = sm + (c & 1) * STG;
        const bf16* Bs = As + ASZ;
        #pragma unroll
        for (int ks = 0; ks < 4; ks++) {
            const int kk = (ks << 4) + (lc << 1);
            uint32_t b[4][2];
            #pragma unroll
            for (int nt = 0; nt < 4; nt++) {
                const bf16* bp = Bs + (warpN + nt * 8 + lr) * 72 + kk;
                b[nt][0] = *reinterpret_cast<const uint32_t*>(bp);
                b[nt][1] = *reinterpret_cast<const uint32_t*>(bp + 8);
            }
            #pragma unroll
            for (int mt = 0; mt < MT; mt++) {
                const bf16* ap = As + (warpM + mt * 16 + lr) * 72 + kk;
                uint32_t a0 = *reinterpret_cast<const uint32_t*>(ap);
                uint32_t a1 = *reinterpret_cast<const uint32_t*>(ap + 8 * 72);
                uint32_t a2 = *reinterpret_cast<const uint32_t*>(ap + 8);
                uint32_t a3 = *reinterpret_cast<const uint32_t*>(ap + 8 * 72 + 8);
                #pragma unroll
                for (int nt = 0; nt < 4; nt++)
                    mma_bf16(acc[mt][nt], a0, a1, a2, a3, b[nt][0], b[nt][1]);
            }
        }
        __syncthreads();
        if (c + 2 < nch) loadtile(c & 1, c + 2);
    }

    float loc = 0.f;
    const float invs = EPI ? (1.f / nstd_p[0]) : 0.f;
    #pragma unroll
    for (int mt = 0; mt < MT; mt++) {
        const int row0 = bm + warpM + mt * 16 + lr;
        #pragma unroll
        for (int nt = 0; nt < 4; nt++) {
            const int col = bn + warpN + nt * 8 + (lc << 1);
            float2 bb = *reinterpret_cast<const float2*>(g.bias + col);
            float v00 = acc[mt][nt][0] + bb.x;
            float v01 = acc[mt][nt][1] + bb.y;
            float v10 = acc[mt][nt][2] + bb.x;
            float v11 = acc[mt][nt][3] + bb.y;
            if (ACT) { v00 = tanhf(v00); v01 = tanhf(v01); v10 = tanhf(v10); v11 = tanhf(v11); }
            if (EPI) {
                float2 x0 = *reinterpret_cast<const float2*>(xs + (size_t)row0 * g.ldc + col);
                float2 x1 = *reinterpret_cast<const float2*>(xs + (size_t)(row0 + 8) * g.ldc + col);
                float r0 = (x0.x - v00) * invs, r1 = (x0.y - v01) * invs;
                float r2 = (x1.x - v10) * invs, r3 = (x1.y - v11) * invs;
                loc += r0 * r0 + r1 * r1 + r2 * r2 + r3 * r3;
            } else if (TSCAT) {
                bf16* Cb = (bf16*)g.C;
                size_t o0 = ((size_t)(row0 & 63) * NB + (row0 >> 6)) * NH + col;
                int row1 = row0 + 8;
                size_t o1 = ((size_t)(row1 & 63) * NB + (row1 >> 6)) * NH + col;
                *reinterpret_cast<__nv_bfloat162*>(Cb + o0) = __floats2bfloat162_rn(v00, v01);
                *reinterpret_cast<__nv_bfloat162*>(Cb + o1) = __floats2bfloat162_rn(v10, v11);
            } else if (OUTBF) {
                bf16* Cb = (bf16*)g.C;
                *reinterpret_cast<__nv_bfloat162*>(Cb + (size_t)row0 * g.ldc + col) = __floats2bfloat162_rn(v00, v01);
                *reinterpret_cast<__nv_bfloat162*>(Cb + (size_t)(row0 + 8) * g.ldc + col) = __floats2bfloat162_rn(v10, v11);
            } else {
                float* Cf = (float*)g.C;
                *reinterpret_cast<float2*>(Cf + (size_t)row0 * g.ldc + col) = make_float2(v00, v01);
                *reinterpret_cast<float2*>(Cf + (size_t)(row0 + 8) * g.ldc + col) = make_float2(v10, v11);
            }
        }
    }
    if (EPI) {
        __syncthreads();
        float tot = block_reduce_sum_256(loc, (float*)smem);
        if (tid == 0) partials[blockIdx.y * gridDim.x + blockIdx.x] = -0.5f * tot;
    }
}

// ---------------- persistent scan (512 threads) --------------------------------
// phase A: 128x128, K=256, 16 warps (warp tile 32x32), 4-stage prefetch-3.
__device__ void gemmA(const bf16* A, const bf16* W, bf16* C,
                      const bf16* fadd, const float* bias,
                      int bm, int bn, char* smem)
{
    constexpr int lda = NT * NL;
    constexpr int ASZ = 128 * 72, STG = 2 * 128 * 72;   // per-stage elems (A+B)
    const int tid = threadIdx.x;
    const int wid = tid >> 5, lane = tid & 31;
    const int lr = lane >> 2, lc = lane & 3;
    bf16* sm = (bf16*)smem;
    const uint32_t sbase = s2u(smem);
    const int warpM = (wid >> 2) * 32;
    const int warpN = (wid & 3) * 32;

    auto loadtile = [&](int s, int c) {
        const int k0 = c << 6;
        uint32_t sA = sbase + (uint32_t)(s * STG) * 2u;
        uint32_t sB = sA + (uint32_t)ASZ * 2u;
        #pragma unroll
        for (int i = 0; i < 2; i++) {
            int idx = tid + (i << 9);
            int m = idx >> 3, k8 = (idx & 7) << 3;
            cp16(sA + (uint32_t)(m * 72 + k8) * 2u, A + (size_t)(bm + m) * lda + k0 + k8);
        }
        #pragma unroll
        for (int i = 0; i < 2; i++) {
            int idx = tid + (i << 9);
            int n = idx >> 3, k8 = (idx & 7) << 3;
            cp16(sB + (uint32_t)(n * 72 + k8) * 2u, W + (size_t)(bn + n) * 256 + k0 + k8);
        }
        asm volatile("cp.async.commit_group;" ::: "memory");
    };

    float acc[2][4][4];
    #pragma unroll
    for (int mt = 0; mt < 2; mt++)
        #pragma unroll
        for (int nt = 0; nt < 4; nt++)
            #pragma unroll
            for (int r = 0; r < 4; r++) acc[mt][nt][r] = 0.f;

    loadtile(0, 0);
    loadtile(1, 1);
    loadtile(2, 2);
    for (int c = 0; c < 4; c++) {
        if (c <= 1)      asm volatile("cp.async.wait_group 2;" ::: "memory");
        else if (c == 2) asm volatile("cp.async.wait_group 1;" ::: "memory");
        else             asm volatile("cp.async.wait_group 0;" ::: "memory");
        __syncthreads();
        if (c + 3 < 4) loadtile(c + 3, c + 3);

        const bf16* As = sm + c * STG;
        const bf16* Bs = As + ASZ;
        #pragma unroll
        for (int ks = 0; ks < 4; ks++) {
            const int kk = (ks << 4) + (lc << 1);
            uint32_t b[4][2];
            #pragma unroll
            for (int nt = 0; nt < 4; nt++) {
                const bf16* bp = Bs + (warpN + nt * 8 + lr) * 72 + kk;
                b[nt][0] = *reinterpret_cast<const uint32_t*>(bp);
                b[nt][1] = *reinterpret_cast<const uint32_t*>(bp + 8);
            }
            #pragma unroll
            for (int mt = 0; mt < 2; mt++) {
                const bf16* ap = As + (warpM + mt * 16 + lr) * 72 + kk;
                uint32_t a0 = *reinterpret_cast<const uint32_t*>(ap);
                uint32_t a1 = *reinterpret_cast<const uint32_t*>(ap + 8 * 72);
                uint32_t a2 = *reinterpret_cast<const uint32_t*>(ap + 8);
                uint32_t a3 = *reinterpret_cast<const uint32_t*>(ap + 8 * 72 + 8);
                #pragma unroll
                for (int nt = 0; nt < 4; nt++)
                    mma_bf16(acc[mt][nt], a0, a1, a2, a3, b[nt][0], b[nt][1]);
            }
        }
    }

    #pragma unroll
    for (int mt = 0; mt < 2; mt++) {
        const int row0 = bm + warpM + mt * 16 + lr;
        #pragma unroll
        for (int nt = 0; nt < 4; nt++) {
            const int gcol = bn + warpN + nt * 8 + (lc << 1);
            float a00, a01, a10, a11;
            if (fadd) {
                __nv_bfloat162 f0 = *reinterpret_cast<const __nv_bfloat162*>(fadd + (size_t)row0 * NH + gcol);
                __nv_bfloat162 f1 = *reinterpret_cast<const __nv_bfloat162*>(fadd + (size_t)(row0 + 8) * NH + gcol);
                a00 = __low2float(f0); a01 = __high2float(f0);
                a10 = __low2float(f1); a11 = __high2float(f1);
            } else {
                float2 bb = *reinterpret_cast<const float2*>(bias + gcol);
                a00 = bb.x; a01 = bb.y; a10 = bb.x; a11 = bb.y;
            }
            float v00 = tanhf(acc[mt][nt][0] + a00);
            float v01 = tanhf(acc[mt][nt][1] + a01);
            float v10 = tanhf(acc[mt][nt][2] + a10);
            float v11 = tanhf(acc[mt][nt][3] + a11);
            *reinterpret_cast<__nv_bfloat162*>(C + (size_t)row0 * NH + gcol) = __floats2bfloat162_rn(v00, v01);
            *reinterpret_cast<__nv_bfloat162*>(C + (size_t)(row0 + 8) * NH + gcol) = __floats2bfloat162_rn(v10, v11);
        }
    }
}

#define SMEMP 147456

__global__ void __launch_bounds__(512)
scan_k(const float* __restrict__ ts, const float* __restrict__ noise,
       float* __restrict__ z, bf16* __restrict__ zs,
       bf16* __restrict__ hf, bf16* __restrict__ hh,
       const bf16* __restrict__ wf1z, const bf16* __restrict__ wh1,
       const bf16* __restrict__ wf2, const bf16* __restrict__ wh2,
       const float* __restrict__ hb1,
       const float* __restrict__ fb2, const float* __restrict__ hb2,
       const bf16* __restrict__ fctx,
       const float* __restrict__ diffv, float* __restrict__ dkl8, unsigned* barct)
{
    extern __shared__ char smem[];
    const int tid = threadIdx.x;
    const int cta = blockIdx.x;             // 0..127
    const int wid = tid >> 5, lane = tid & 31;
    const int lr = lane >> 2, lc = lane & 3;

    // phase A tile: 8 bm-groups x 16 bn-groups
    const int a_bm = (cta >> 4) * 128;
    const int a_bnI = cta & 15;             // <8: f, >=8: h

    // phase B tile: 64 x 32 (both drift and prior); K split over 2 warp-halves
    const int b_bm = (cta >> 3) * 64;
    const int b_ng = cta & 7;
    const int b_bn = b_ng * 32;
    const int kg  = tid >> 8;               // 0: k 0..511, 1: k 512..1023
    const int tkg = tid & 255;
    const int wi  = wid & 7;

    // phase B smem: per kg 2 stages of (Af64 Ah64 Bf32 Bh32)x72; partial area after
    constexpr int AF = 0, AH = 64 * 72, BF = 128 * 72, BH = 128 * 72 + 32 * 72;
    constexpr int STG2 = 192 * 72;          // elems/stage (27648 B)
    constexpr int PART = 110592;            // bytes: 4 stages end
    constexpr int SRED = PART + 16384;
    bf16* sm = (bf16*)smem;
    const uint32_t sbase = s2u(smem);

    unsigned tgt = 0;

    for (int t = 0; t < NT - 1; t++) {
        // ---------------- phase A ----------------
        const bf16* Az = zs + (size_t)t * NL;   // rows: b, lda = NT*NL
        if (a_bnI < 8)
            gemmA(Az, wf1z, hf, fctx + (size_t)(t + 1) * NB * NH, nullptr,
                  a_bm, a_bnI * 128, smem);
        else
            gemmA(Az, wh1, hh, nullptr, hb1, a_bm, (a_bnI - 8) * 128, smem);

        tgt += 128; gbar(barct, tgt);

        // ---------------- phase B ----------------
        auto loadB = [&](int s, int cg) {
            const int k0 = cg << 6;
            uint32_t base = sbase + (uint32_t)((kg * 2 + s) * STG2) * 2u;
            #pragma unroll
            for (int i = 0; i < 2; i++) {
                int idx = tkg + (i << 8);
                int m = idx >> 3, k8 = (idx & 7) << 3;
                cp16(base + (uint32_t)(AF + m * 72 + k8) * 2u, hf + (size_t)(b_bm + m) * NH + k0 + k8);
                cp16(base + (uint32_t)(AH + m * 72 + k8) * 2u, hh + (size_t)(b_bm + m) * NH + k0 + k8);
            }
            {
                int n = tkg >> 3, k8 = (tkg & 7) << 3;
                cp16(base + (uint32_t)(BF + n * 72 + k8) * 2u, wf2 + (size_t)(b_bn + n) * NH + k0 + k8);
                cp16(base + (uint32_t)(BH + n * 72 + k8) * 2u, wh2 + (size_t)(b_bn + n) * NH + k0 + k8);
            }
            asm volatile("cp.async.commit_group;" ::: "memory");
        };

        float ad[2][4], ap_[2][4];
        #pragma unroll
        for (int nt = 0; nt < 2; nt++)
            #pragma unroll
            for (int r = 0; r < 4; r++) { ad[nt][r] = 0.f; ap_[nt][r] = 0.f; }

        const int warpM = (wi & 3) * 16;        // 4 m-warps per kg
        const int warpNl = (wi >> 2) * 16;      // 2 n-warps per kg
        const int cbase = kg * 8;
        loadB(0, cbase + 0);
        loadB(1, cbase + 1);
        for (int c = 0; c < 8; c++) {
            if (c < 7) asm volatile("cp.async.wait_group 1;" ::: "memory");
            else       asm volatile("cp.async.wait_group 0;" ::: "memory");
            __syncthreads();

            const bf16* st = sm + (kg * 2 + (c & 1)) * STG2;
            #pragma unroll
            for (int ks = 0; ks < 4; ks++) {
                const int kk = (ks << 4) + (lc << 1);
                const bf16* af = st + AF + (warpM + lr) * 72 + kk;
                uint32_t fa0 = *reinterpret_cast<const uint32_t*>(af);
                uint32_t fa1 = *reinterpret_cast<const uint32_t*>(af + 8 * 72);
                uint32_t fa2 = *reinterpret_cast<const uint32_t*>(af + 8);
                uint32_t fa3 = *reinterpret_cast<const uint32_t*>(af + 8 * 72 + 8);
                const bf16* ah = st + AH + (warpM + lr) * 72 + kk;
                uint32_t ha0 = *reinterpret_cast<const uint32_t*>(ah);
                uint32_t ha1 = *reinterpret_cast<const uint32_t*>(ah + 8 * 72);
                uint32_t ha2 = *reinterpret_cast<const uint32_t*>(ah + 8);
                uint32_t ha3 = *reinterpret_cast<const uint32_t*>(ah + 8 * 72 + 8);
                #pragma unroll
                for (int nt = 0; nt < 2; nt++) {
                    const bf16* bf_ = st + BF + (warpNl + nt * 8 + lr) * 72 + kk;
                    uint32_t b0 = *reinterpret_cast<const uint32_t*>(bf_);
                    uint32_t b1 = *reinterpret_cast<const uint32_t*>(bf_ + 8);
                    mma_bf16(ad[nt], fa0, fa1, fa2, fa3, b0, b1);
                    const bf16* bh_ = st + BH + (warpNl + nt * 8 + lr) * 72 + kk;
                    uint32_t c0 = *reinterpret_cast<const uint32_t*>(bh_);
                    uint32_t c1 = *reinterpret_cast<const uint32_t*>(bh_ + 8);
                    mma_bf16(ap_[nt], ha0, ha1, ha2, ha3, c0, c1);
                }
            }
            __syncthreads();
            if (c + 2 < 8) loadB(c & 1, cbase + c + 2);
        }

        // ---- merge kg partials (fixed order: kg0 + kg1 -> deterministic) ----
        float* sp = (float*)(smem + PART);
        if (kg == 1) {
            #pragma unroll
            for (int nt = 0; nt < 2; nt++)
                #pragma unroll
                for (int j = 0; j < 4; j++) {
                    sp[(wi * 16 + nt * 8 + j * 2 + 0) * 32 + lane] = ad[nt][j];
                    sp[(wi * 16 + nt * 8 + j * 2 + 1) * 32 + lane] = ap_[nt][j];
                }
        }
        __syncthreads();

        // ---- fused step update (kg0 warps only) ----
        const float dt = ts[t + 1] - ts[t];
        const float sq = sqrtf(dt);
        float* sred = (float*)(smem + SRED);    // 128 floats
        if (kg == 0) {
            #pragma unroll
            for (int nt = 0; nt < 2; nt++)
                #pragma unroll
                for (int j = 0; j < 4; j++) {
                    ad[nt][j]  += sp[(wi * 16 + nt * 8 + j * 2 + 0) * 32 + lane];
                    ap_[nt][j] += sp[(wi * 16 + nt * 8 + j * 2 + 1) * 32 + lane];
                }

            float pr_lo = 0.f, pr_hi = 0.f;
            #pragma unroll
            for (int nt = 0; nt < 2; nt++) {
                const int col = b_bn + warpNl + nt * 8 + (lc << 1);
                const float fb0 = fb2[col], fb1v = fb2[col + 1];
                const float hb0 = hb2[col], hb1v = hb2[col + 1];
                float d00 = ad[nt][0] + fb0, d01 = ad[nt][1] + fb1v;
                float d10 = ad[nt][2] + fb0, d11 = ad[nt][3] + fb1v;
                float p00 = ap_[nt][0] + hb0, p01 = ap_[nt][1] + hb1v;
                float p10 = ap_[nt][2] + hb0, p11 = ap_[nt][3] + hb1v;

                const float df0 = diffv[col], df1 = diffv[col + 1];
                float den0 = fabsf(df0) > EPSV ? df0 : ((df0 > 0.f) - (df0 < 0.f)) * EPSV;
                float den1 = fabsf(df1) > EPSV ? df1 : ((df1 > 0.f) - (df1 < 0.f)) * EPSV;
                float r00 = (d00 - p00) / den0, r01 = (d01 - p01) / den1;
                float r10 = (d10 - p10) / den0, r11 = (d11 - p11) / den1;
                pr_lo += r00 * r00 + r01 * r01;
                pr_hi += r10 * r10 + r11 * r11;

                const int b0r = b_bm + warpM + lr, b1r = b0r + 8;
                {
                    size_t zi = (size_t)b0r * NL + col;
                    float e0 = noise[((size_t)t * NB + b0r) * NL + col];
                    float e1 = noise[((size_t)t * NB + b0r) * NL + col + 1];
                    float zn0 = z[zi] + d00 * dt + df0 * sq * e0;
                    float zn1 = z[zi + 1] + d01 * dt + df1 * sq * e1;
                    z[zi] = zn0; z[zi + 1] = zn1;
                    *reinterpret_cast<__nv_bfloat162*>(zs + ((size_t)b0r * NT + t + 1) * NL + col)
                        = __floats2bfloat162_rn(zn0, zn1);
                }
                {
                    size_t zi = (size_t)b1r * NL + col;
                    float e0 = noise[((size_t)t * NB + b1r) * NL + col];
                    float e1 = noise[((size_t)t * NB + b1r) * NL + col + 1];
                    float zn0 = z[zi] + d10 * dt + df0 * sq * e0;
                    float zn1 = z[zi + 1] + d11 * dt + df1 * sq * e1;
                    z[zi] = zn0; z[zi + 1] = zn1;
                    *reinterpret_cast<__nv_bfloat162*>(zs + ((size_t)b1r * NT + t + 1) * NL + col)
                        = __floats2bfloat162_rn(zn0, zn1);
                }
            }

            pr_lo += __shfl_xor_sync(0xffffffff, pr_lo, 1);
            pr_lo += __shfl_xor_sync(0xffffffff, pr_lo, 2);
            pr_hi += __shfl_xor_sync(0xffffffff, pr_hi, 1);
            pr_hi += __shfl_xor_sync(0xffffffff, pr_hi, 2);
            const int ngrp = wi >> 2;
            if (lc == 0) {
                sred[(warpM + lr) * 2 + ngrp] = pr_lo;
                sred[(warpM + lr + 8) * 2 + ngrp] = pr_hi;
            }
        }
        __syncthreads();
        if (tid < 64)
            dkl8[b_ng * NB + b_bm + tid] += (sred[tid * 2] + sred[tid * 2 + 1]) * dt;

        tgt += 128; gbar(barct, tgt);
    }
}

// ---------------- prologue kernels --------------------------------------------
__global__ void transp_k(const float* __restrict__ W, bf16* __restrict__ Wt, int K, int N) {
    __shared__ float t[32][33];
    int n0 = blockIdx.x * 32, k0 = blockIdx.y * 32;
    int tx = threadIdx.x, ty = threadIdx.y;  // 32 x 8
    #pragma unroll
    for (int j = 0; j < 4; j++)
        t[ty + j * 8][tx] = W[(size_t)(k0 + ty + j * 8) * N + n0 + tx];
    __syncthreads();
    #pragma unroll
    for (int j = 0; j < 4; j++)
        Wt[(size_t)(n0 + ty + j * 8) * K + k0 + tx] = __float2bfloat16(t[tx][ty + j * 8]);
}

__global__ void copy_xs_k(const float* __restrict__ xs, bf16* __restrict__ ctx,
                          bf16* __restrict__ xst) {
    size_t i = (size_t)blockIdx.x * 256 + threadIdx.x;
    size_t bt = i >> 8, d = i & 255;
    bf16 v = __float2bfloat16(xs[i]);
    ctx[bt * 512 + 256 + d] = v;
    xst[i] = v;
}

__global__ void diffv_k(const float* __restrict__ gamma, float* __restrict__ diffv) {
    int l = threadIdx.x;
    diffv[l] = sqrtf(2.f / (BETAV * gamma[l]));
}

__global__ void z0_k(const float* __restrict__ q, const float* __restrict__ eps0,
                     const float* __restrict__ pm, const float* __restrict__ pl,
                     float* __restrict__ z, bf16* __restrict__ zs,
                     float* __restrict__ kl0, float* __restrict__ dkl8, unsigned* barct)
{
    __shared__ float sh[256];
    int b = blockIdx.x, l = threadIdx.x;
    if (b == 0) {
        if (l == 0) *barct = 0;
        #pragma unroll
        for (int i = 0; i < 32; i++) dkl8[l + i * 256] = 0.f;
    }
    float qm = q[b * 512 + l];
    float ql = q[b * 512 + 256 + l];
    float z0 = qm + expf(ql) * eps0[b * NL + l];
    z[b * NL + l] = z0;
    zs[(size_t)b * NT * NL + l] = __float2bfloat16(z0);
    float pmv = pm[l], plv = pl[l];
    float dm = qm - pmv;
    float term = plv - ql + (expf(2.f * ql) + dm * dm) / (2.f * expf(2.f * plv)) - 0.5f;
    float s = block_reduce_sum_256(term, sh);
    if (l == 0) kl0[b] = s;
}

__global__ void finalize_k(const float* __restrict__ partials, int np,
                           const float* __restrict__ dkl8, const float* __restrict__ kl0,
                           const float* __restrict__ nstd_p, float* __restrict__ out)
{
    __shared__ float sh[256];
    int tid = threadIdx.x;
    float s = 0.f;
    for (int i = tid; i < np; i += 256) s += partials[i];
    float tot = block_reduce_sum_256(s, sh);

    float s2 = 0.f;
    for (int i = tid; i < 8 * NB; i += 256) s2 += dkl8[i];
    float dkl_tot = block_reduce_sum_256(s2, sh);

    float s3 = 0.f;
    for (int i = tid; i < NB; i += 256) s3 += kl0[i];
    float kl0_tot = block_reduce_sum_256(s3, sh);

    if (tid == 0) {
        float nstd = nstd_p[0];
        float cst = (float)NT * (float)ND * (-logf(nstd) - 0.5f * LOG2PI);
        float log_pxs = tot / (float)NB + cst;
        out[0] = -log_pxs;
        out[1] = dkl_tot / (float)NB + kl0_tot / (float)NB;
    }
}

// ---------------- launch ------------------------------------------------------
#define SMEM128 (2 * (128*72 + 128*72) * 2)   // 73728

extern "C" void kernel_launch(void* const* d_in, const int* in_sizes, int n_in,
                              void* d_out, int out_size)
{
    const float* xs        = (const float*)d_in[0];
    const float* ts        = (const float*)d_in[1];
    const float* noise_std = (const float*)d_in[2];
    const float* eps0      = (const float*)d_in[3];
    const float* noise     = (const float*)d_in[4];
    const float* enc_w1    = (const float*)d_in[5];
    const float* enc_b1    = (const float*)d_in[6];
    const float* enc_w2    = (const float*)d_in[7];
    const float* enc_b2    = (const float*)d_in[8];
    const float* qz0_w     = (const float*)d_in[9];
    const float* qz0_b     = (const float*)d_in[10];
    const float* f_w1      = (const float*)d_in[11];
    const float* f_b1      = (const float*)d_in[12];
    const float* f_w2      = (const float*)d_in[13];
    const float* f_b2      = (const float*)d_in[14];
    const float* h_w1      = (const float*)d_in[15];
    const float* h_b1      = (const float*)d_in[16];
    const float* h_w2      = (const float*)d_in[17];
    const float* h_b2      = (const float*)d_in[18];
    const float* proj_w    = (const float*)d_in[19];
    const float* proj_b    = (const float*)d_in[20];
    const float* pz0_mean  = (const float*)d_in[21];
    const float* pz0_logstd= (const float*)d_in[22];
    const float* gamma     = (const float*)d_in[23];

    bf16 *y1, *ctx, *xst, *zs, *hf, *hh, *wtb, *fctx;
    float *z, *q, *dkl8, *kl0, *diffv, *partials;
    unsigned* barct;
    cudaGetSymbolAddress((void**)&y1, g_y1);
    cudaGetSymbolAddress((void**)&ctx, g_ctx);
    cudaGetSymbolAddress((void**)&xst, g_xst);
    cudaGetSymbolAddress((void**)&zs, g_zs);
    cudaGetSymbolAddress((void**)&z, g_z);
    cudaGetSymbolAddress((void**)&hf, g_hf);
    cudaGetSymbolAddress((void**)&hh, g_hh);
    cudaGetSymbolAddress((void**)&q, g_q);
    cudaGetSymbolAddress((void**)&fctx, g_fctx);
    cudaGetSymbolAddress((void**)&wtb, g_wtb);
    cudaGetSymbolAddress((void**)&dkl8, g_dkl8);
    cudaGetSymbolAddress((void**)&kl0, g_kl0);
    cudaGetSymbolAddress((void**)&diffv, g_diffv);
    cudaGetSymbolAddress((void**)&partials, g_partials);
    cudaGetSymbolAddress((void**)&barct, g_barct);

    cudaFuncSetAttribute(gemm_bf<128,1,1,0,0>, cudaFuncAttributeMaxDynamicSharedMemorySize, SMEM128);
    cudaFuncSetAttribute(gemm_bf<128,0,1,0,0>, cudaFuncAttributeMaxDynamicSharedMemorySize, SMEM128);
    cudaFuncSetAttribute(gemm_bf<128,0,0,0,0>, cudaFuncAttributeMaxDynamicSharedMemorySize, SMEM128);
    cudaFuncSetAttribute(gemm_bf<128,0,0,1,0>, cudaFuncAttributeMaxDynamicSharedMemorySize, SMEM128);
    cudaFuncSetAttribute(gemm_bf<128,0,0,0,1>, cudaFuncAttributeMaxDynamicSharedMemorySize, SMEM128);
    cudaFuncSetAttribute(scan_k, cudaFuncAttributeMaxDynamicSharedMemorySize, SMEMP);

    const int M = NB * NT;
    dim3 tb(32, 8);

    // ---- weights: transpose + bf16 ----
    transp_k<<<dim3(NH/32,  ND/32), tb>>>(enc_w1, wtb + W_ENC1, ND,  NH);
    transp_k<<<dim3(NL/32,  NH/32), tb>>>(enc_w2, wtb + W_ENC2, NH,  NL);
    transp_k<<<dim3(512/32, 512/32),tb>>>(qz0_w,  wtb + W_QZ0,  512, 512);
    transp_k<<<dim3(NH/32,  256/32),tb>>>(f_w1,            wtb + W_F1Z, 256, NH);
    transp_k<<<dim3(NH/32,  512/32),tb>>>(f_w1 + 256 * NH, wtb + W_F1C, 512, NH);
    transp_k<<<dim3(NL/32,  NH/32), tb>>>(f_w2,   wtb + W_F2,   NH,  NL);
    transp_k<<<dim3(NH/32,  NL/32), tb>>>(h_w1,   wtb + W_H1,   NL,  NH);
    transp_k<<<dim3(NL/32,  NH/32), tb>>>(h_w2,   wtb + W_H2,   NH,  NL);
    transp_k<<<dim3(ND/32,  NL/32), tb>>>(proj_w, wtb + W_PROJ, NL,  ND);
    copy_xs_k<<<(int)((size_t)M * ND / 256), 256>>>(xs, ctx, xst);

    GArgs zg{};

    // ---- encoder ----
    {
        GArgs a{xst, ND, wtb + W_ENC1, enc_b1, y1, NH, ND};
        gemm_bf<128,1,1,0,0><<<dim3(NH/128, M/128), 256, SMEM128>>>(a, a, M/128, nullptr, nullptr, nullptr);
    }
    {
        GArgs a{y1, NH, wtb + W_ENC2, enc_b2, ctx, 512, NH};
        gemm_bf<128,0,1,0,0><<<dim3(NL/128, M/128), 256, SMEM128>>>(a, a, M/128, nullptr, nullptr, nullptr);
    }

    // ---- fctx[t][b][:] = ctx[b][t][:] @ f_w1[256:768] + f_b1 (bf16, t-scatter) ----
    {
        GArgs a{ctx, 512, wtb + W_F1C, f_b1, fctx, NH, 512};
        gemm_bf<128,0,0,0,1><<<dim3(NH/128, M/128), 256, SMEM128>>>(a, a, M/128, nullptr, nullptr, nullptr);
    }

    // ---- q = ctx[:,0,:] @ qz0_w + qz0_b ----
    {
        GArgs a{ctx, NT * 512, wtb + W_QZ0, qz0_b, q, 512, 512};
        gemm_bf<128,0,0,0,0><<<dim3(512/128, NB/128), 256, SMEM128>>>(a, a, NB/128, nullptr, nullptr, nullptr);
    }

    z0_k<<<NB, 256>>>(q, eps0, pz0_mean, pz0_logstd, z, zs, kl0, dkl8, barct);
    diffv_k<<<1, NL>>>(gamma, diffv);

    // ---- persistent scan: 512 threads, k-split phase B ----
    scan_k<<<128, 512, SMEMP>>>(ts, noise, z, zs, hf, hh,
                                wtb + W_F1Z, wtb + W_H1, wtb + W_F2, wtb + W_H2,
                                h_b1, f_b2, h_b2, fctx, diffv, dkl8, barct);

    // ---- decoder fused with NLL reduction ----
    {
        GArgs a{zs, NL, wtb + W_PROJ, proj_b, nullptr, ND, NL};
        gemm_bf<128,0,0,1,0><<<dim3(ND/128, M/128), 256, SMEM128>>>(a, zg, M/128, xs, noise_std, partials);
    }

    finalize_k<<<1, 256>>>(partials, (M/128) * (ND/128), dkl8, kl0, noise_std, (float*)d_out);

    (void)in_sizes; (void)n_in; (void)out_size;
}

// round 12
// speedup vs baseline: 1.0144x; 1.0144x over previous
#include <cuda_runtime.h>
#include <cuda_bf16.h>
#include <math.h>
#include <stdint.h>

// ---------------- problem dims ------------------------------------------------
#define NB 1024
#define NT 64
#define ND 256
#define NL 256
#define NH 1024
#define EPSV 1e-7f
#define LOG2PI 1.8378770664093453f
#define BETAV (1.0f/3.0f)

typedef __nv_bfloat16 bf16;

// ---------------- scratch (device globals) ------------------------------------
__device__ __align__(16) bf16  g_y1[(size_t)NB * NT * NH];
__device__ __align__(16) bf16  g_ctx[(size_t)NB * NT * 512];
__device__ __align__(16) bf16  g_xst[(size_t)NB * NT * ND];
__device__ __align__(16) bf16  g_zs[(size_t)NB * NT * NL];
__device__ __align__(16) float g_z[NB * NL];
__device__ __align__(16) bf16  g_hf[NB * NH];
__device__ __align__(16) bf16  g_hh[NB * NH];
__device__ __align__(16) float g_q[NB * 512];
__device__ __align__(16) bf16  g_fctx[(size_t)NT * NB * NH];   // [t][b][1024] bf16
__device__ __align__(16) bf16  g_wtb[2424832];
__device__ float g_dkl8[8 * NB];
__device__ float g_kl0[NB];
__device__ float g_diffv[NL];
__device__ float g_partials[4096];
__device__ unsigned g_flagA[NT * 8];   // phase-A done counters per (t, row-group)
__device__ unsigned g_flagB[NT * 8];   // phase-B done counters per (t, row-group)

// weight offsets in g_wtb (elements), stored transposed [N][K]
#define W_ENC1 0
#define W_ENC2 262144
#define W_QZ0  524288
#define W_F1Z  786432      // f_w1 rows 0..255   -> [1024][256]
#define W_F1C  1048576     // f_w1 rows 256..767 -> [1024][512]
#define W_F2   1572864
#define W_H1   1835008
#define W_H2   2097152
#define W_PROJ 2359296

// ---------------- helpers -----------------------------------------------------
__device__ __forceinline__ uint32_t s2u(const void* p) {
    uint32_t a;
    asm("{ .reg .u64 t; cvta.to.shared.u64 t, %1; cvt.u32.u64 %0, t; }" : "=r"(a) : "l"(p));
    return a;
}
__device__ __forceinline__ void cp16(uint32_t saddr, const void* g) {
    asm volatile("cp.async.cg.shared.global [%0], [%1], 16;" :: "r"(saddr), "l"(g));
}
__device__ __forceinline__ void mma_bf16(float* c, uint32_t a0, uint32_t a1, uint32_t a2, uint32_t a3,
                                         uint32_t b0, uint32_t b1) {
    asm volatile("mma.sync.aligned.m16n8k16.row.col.f32.bf16.bf16.f32 "
                 "{%0,%1,%2,%3},{%4,%5,%6,%7},{%8,%9},{%0,%1,%2,%3};"
                 : "+f"(c[0]), "+f"(c[1]), "+f"(c[2]), "+f"(c[3])
                 : "r"(a0), "r"(a1), "r"(a2), "r"(a3), "r"(b0), "r"(b1));
}
__device__ __forceinline__ float block_reduce_sum_256(float v, float* sh) {
    int tid = threadIdx.x;
    sh[tid] = v;
    __syncthreads();
    #pragma unroll
    for (int s = 128; s > 0; s >>= 1) {
        if (tid < s) sh[tid] += sh[tid + s];
        __syncthreads();
    }
    float r = sh[0];
    __syncthreads();
    return r;
}
// dataflow flags: release-arrive / acquire-spin on a per-row-group counter
__device__ __forceinline__ void wait_flag(unsigned* f, unsigned tgt) {
    if (threadIdx.x == 0) {
        unsigned v;
        do {
            asm volatile("ld.acquire.gpu.u32 %0, [%1];" : "=r"(v) : "l"(f) : "memory");
        } while (v < tgt);
    }
    __syncthreads();
}
__device__ __forceinline__ void arrive_flag(unsigned* f) {
    __syncthreads();   // all threads' prior stores ordered before the release
    if (threadIdx.x == 0)
        asm volatile("red.release.gpu.add.u32 [%0], 1;" :: "l"(f) : "memory");
}

// ---------------- standalone bf16 GEMM (encoder / q / fctx / decoder) ---------
struct GArgs {
    const bf16* A; int lda;
    const bf16* W;            // transposed [N][K], row stride = K
    const float* bias;
    void* C; int ldc;
    int K;
};

// STOREs: OUTBF=1 -> bf16 linear; EPI=1 -> fused NLL (no store);
// TSCAT=1 -> bf16 store scattered to [t][b][1024] (m = b*64+t)
template<int BMT, int ACT, int OUTBF, int EPI, int TSCAT>
__global__ void __launch_bounds__(256)
gemm_bf(GArgs g0, GArgs g1, int mSplit,
        const float* __restrict__ xs, const float* __restrict__ nstd_p,
        float* __restrict__ partials)
{
    extern __shared__ char smem[];
    constexpr int MT  = (BMT + 31) / 32;
    constexpr int ASZ = BMT * 72;
    constexpr int BSZ = 128 * 72;
    constexpr int STG = ASZ + BSZ;

    const int tid  = threadIdx.x;
    const int wid  = tid >> 5;
    const int lane = tid & 31;
    const int lr   = lane >> 2;
    const int lc   = lane & 3;

    const bool grp1 = ((int)blockIdx.y >= mSplit);
    const GArgs g = grp1 ? g1 : g0;
    const int bm = (grp1 ? ((int)blockIdx.y - mSplit) : (int)blockIdx.y) * BMT;
    const int bn = (int)blockIdx.x * 128;

    bf16* sm = (bf16*)smem;
    const uint32_t sbase = s2u(smem);
    const int warpM = (wid >> 2) * (BMT / 2);
    const int warpN = (wid & 3) * 32;

    auto loadtile = [&](int s, int c) {
        const int k0 = c << 6;
        uint32_t sA = sbase + (uint32_t)(s * STG) * 2u;
        uint32_t sB = sA + (uint32_t)ASZ * 2u;
        const bf16* Ag = g.A + (size_t)bm * g.lda + k0;
        #pragma unroll
        for (int i = 0; i < BMT / 32; i++) {
            int idx = tid + (i << 8);
            int m = idx >> 3, k8 = (idx & 7) << 3;
            cp16(sA + (uint32_t)(m * 72 + k8) * 2u, Ag + (size_t)m * g.lda + k8);
        }
        const bf16* Wg = g.W + (size_t)bn * g.K + k0;
        #pragma unroll
        for (int i = 0; i < 4; i++) {
            int idx = tid + (i << 8);
            int n = idx >> 3, k8 = (idx & 7) << 3;
            cp16(sB + (uint32_t)(n * 72 + k8) * 2u, Wg + (size_t)n * g.K + k8);
        }
        asm volatile("cp.async.commit_group;" ::: "memory");
    };

    float acc[MT][4][4];
    #pragma unroll
    for (int mt = 0; mt < MT; mt++)
        #pragma unroll
        for (int nt = 0; nt < 4; nt++)
            #pragma unroll
            for (int r = 0; r < 4; r++) acc[mt][nt][r] = 0.f;

    const int nch = g.K >> 6;
    loadtile(0, 0);
    if (nch > 1) loadtile(1, 1);

    for (int c = 0; c < nch; c++) {
        if (c + 1 < nch) asm volatile("cp.async.wait_group 1;" ::: "memory");
        else             asm volatile("cp.async.wait_group 0;" ::: "memory");
        __syncthreads();
        const bf16* As = sm + (c & 1) * STG;
        const bf16* Bs = As + ASZ;
        #pragma unroll
        for (int ks = 0; ks < 4; ks++) {
            const int kk = (ks << 4) + (lc << 1);
            uint32_t b[4][2];
            #pragma unroll
            for (int nt = 0; nt < 4; nt++) {
                const bf16* bp = Bs + (warpN + nt * 8 + lr) * 72 + kk;
                b[nt][0] = *reinterpret_cast<const uint32_t*>(bp);
                b[nt][1] = *reinterpret_cast<const uint32_t*>(bp + 8);
            }
            #pragma unroll
            for (int mt = 0; mt < MT; mt++) {
                const bf16* ap = As + (warpM + mt * 16 + lr) * 72 + kk;
                uint32_t a0 = *reinterpret_cast<const uint32_t*>(ap);
                uint32_t a1 = *reinterpret_cast<const uint32_t*>(ap + 8 * 72);
                uint32_t a2 = *reinterpret_cast<const uint32_t*>(ap + 8);
                uint32_t a3 = *reinterpret_cast<const uint32_t*>(ap + 8 * 72 + 8);
                #pragma unroll
                for (int nt = 0; nt < 4; nt++)
                    mma_bf16(acc[mt][nt], a0, a1, a2, a3, b[nt][0], b[nt][1]);
            }
        }
        __syncthreads();
        if (c + 2 < nch) loadtile(c & 1, c + 2);
    }

    float loc = 0.f;
    const float invs = EPI ? (1.f / nstd_p[0]) : 0.f;
    #pragma unroll
    for (int mt = 0; mt < MT; mt++) {
        const int row0 = bm + warpM + mt * 16 + lr;
        #pragma unroll
        for (int nt = 0; nt < 4; nt++) {
            const int col = bn + warpN + nt * 8 + (lc << 1);
            float2 bb = *reinterpret_cast<const float2*>(g.bias + col);
            float v00 = acc[mt][nt][0] + bb.x;
            float v01 = acc[mt][nt][1] + bb.y;
            float v10 = acc[mt][nt][2] + bb.x;
            float v11 = acc[mt][nt][3] + bb.y;
            if (ACT) { v00 = tanhf(v00); v01 = tanhf(v01); v10 = tanhf(v10); v11 = tanhf(v11); }
            if (EPI) {
                float2 x0 = *reinterpret_cast<const float2*>(xs + (size_t)row0 * g.ldc + col);
                float2 x1 = *reinterpret_cast<const float2*>(xs + (size_t)(row0 + 8) * g.ldc + col);
                float r0 = (x0.x - v00) * invs, r1 = (x0.y - v01) * invs;
                float r2 = (x1.x - v10) * invs, r3 = (x1.y - v11) * invs;
                loc += r0 * r0 + r1 * r1 + r2 * r2 + r3 * r3;
            } else if (TSCAT) {
                bf16* Cb = (bf16*)g.C;
                size_t o0 = ((size_t)(row0 & 63) * NB + (row0 >> 6)) * NH + col;
                int row1 = row0 + 8;
                size_t o1 = ((size_t)(row1 & 63) * NB + (row1 >> 6)) * NH + col;
                *reinterpret_cast<__nv_bfloat162*>(Cb + o0) = __floats2bfloat162_rn(v00, v01);
                *reinterpret_cast<__nv_bfloat162*>(Cb + o1) = __floats2bfloat162_rn(v10, v11);
            } else if (OUTBF) {
                bf16* Cb = (bf16*)g.C;
                *reinterpret_cast<__nv_bfloat162*>(Cb + (size_t)row0 * g.ldc + col) = __floats2bfloat162_rn(v00, v01);
                *reinterpret_cast<__nv_bfloat162*>(Cb + (size_t)(row0 + 8) * g.ldc + col) = __floats2bfloat162_rn(v10, v11);
            } else {
                float* Cf = (float*)g.C;
                *reinterpret_cast<float2*>(Cf + (size_t)row0 * g.ldc + col) = make_float2(v00, v01);
                *reinterpret_cast<float2*>(Cf + (size_t)(row0 + 8) * g.ldc + col) = make_float2(v10, v11);
            }
        }
    }
    if (EPI) {
        __syncthreads();
        float tot = block_reduce_sum_256(loc, (float*)smem);
        if (tid == 0) partials[blockIdx.y * gridDim.x + blockIdx.x] = -0.5f * tot;
    }
}

// ---------------- persistent scan ---------------------------------------------
// phase A: 128x128, K=256 (4 chunks, 4-stage pipeline, prefetch 3, 1 sync/chunk).
__device__ void gemmA(const bf16* A, const bf16* W, bf16* C,
                      const bf16* fadd, const float* bias,
                      int bm, int bn, char* smem)
{
    constexpr int lda = NT * NL;
    constexpr int ASZ = 128 * 72, STG = 2 * 128 * 72;   // per-stage elems (A+B)
    const int tid = threadIdx.x;
    const int wid = tid >> 5, lane = tid & 31;
    const int lr = lane >> 2, lc = lane & 3;
    bf16* sm = (bf16*)smem;
    const uint32_t sbase = s2u(smem);
    const int warpM = (wid >> 2) * 64;
    const int warpN = (wid & 3) * 32;

    auto loadtile = [&](int s, int c) {
        const int k0 = c << 6;
        uint32_t sA = sbase + (uint32_t)(s * STG) * 2u;
        uint32_t sB = sA + (uint32_t)ASZ * 2u;
        #pragma unroll
        for (int i = 0; i < 4; i++) {
            int idx = tid + (i << 8);
            int m = idx >> 3, k8 = (idx & 7) << 3;
            cp16(sA + (uint32_t)(m * 72 + k8) * 2u, A + (size_t)(bm + m) * lda + k0 + k8);
        }
        #pragma unroll
        for (int i = 0; i < 4; i++) {
            int idx = tid + (i << 8);
            int n = idx >> 3, k8 = (idx & 7) << 3;
            cp16(sB + (uint32_t)(n * 72 + k8) * 2u, W + (size_t)(bn + n) * 256 + k0 + k8);
        }
        asm volatile("cp.async.commit_group;" ::: "memory");
    };

    float acc[4][4][4];
    #pragma unroll
    for (int mt = 0; mt < 4; mt++)
        #pragma unroll
        for (int nt = 0; nt < 4; nt++)
            #pragma unroll
            for (int r = 0; r < 4; r++) acc[mt][nt][r] = 0.f;

    loadtile(0, 0);
    loadtile(1, 1);
    loadtile(2, 2);
    for (int c = 0; c < 4; c++) {
        if (c <= 1)      asm volatile("cp.async.wait_group 2;" ::: "memory");
        else if (c == 2) asm volatile("cp.async.wait_group 1;" ::: "memory");
        else             asm volatile("cp.async.wait_group 0;" ::: "memory");
        __syncthreads();
        if (c + 3 < 4) loadtile(c + 3, c + 3);

        const bf16* As = sm + c * STG;
        const bf16* Bs = As + ASZ;
        #pragma unroll
        for (int ks = 0; ks < 4; ks++) {
            const int kk = (ks << 4) + (lc << 1);
            uint32_t b[4][2];
            #pragma unroll
            for (int nt = 0; nt < 4; nt++) {
                const bf16* bp = Bs + (warpN + nt * 8 + lr) * 72 + kk;
                b[nt][0] = *reinterpret_cast<const uint32_t*>(bp);
                b[nt][1] = *reinterpret_cast<const uint32_t*>(bp + 8);
            }
            #pragma unroll
            for (int mt = 0; mt < 4; mt++) {
                const bf16* ap = As + (warpM + mt * 16 + lr) * 72 + kk;
                uint32_t a0 = *reinterpret_cast<const uint32_t*>(ap);
                uint32_t a1 = *reinterpret_cast<const uint32_t*>(ap + 8 * 72);
                uint32_t a2 = *reinterpret_cast<const uint32_t*>(ap + 8);
                uint32_t a3 = *reinterpret_cast<const uint32_t*>(ap + 8 * 72 + 8);
                #pragma unroll
                for (int nt = 0; nt < 4; nt++)
                    mma_bf16(acc[mt][nt], a0, a1, a2, a3, b[nt][0], b[nt][1]);
            }
        }
    }

    #pragma unroll
    for (int mt = 0; mt < 4; mt++) {
        const int row0 = bm + warpM + mt * 16 + lr;
        #pragma unroll
        for (int nt = 0; nt < 4; nt++) {
            const int gcol = bn + warpN + nt * 8 + (lc << 1);
            float a00, a01, a10, a11;
            if (fadd) {
                __nv_bfloat162 f0 = *reinterpret_cast<const __nv_bfloat162*>(fadd + (size_t)row0 * NH + gcol);
                __nv_bfloat162 f1 = *reinterpret_cast<const __nv_bfloat162*>(fadd + (size_t)(row0 + 8) * NH + gcol);
                a00 = __low2float(f0); a01 = __high2float(f0);
                a10 = __low2float(f1); a11 = __high2float(f1);
            } else {
                float2 bb = *reinterpret_cast<const float2*>(bias + gcol);
                a00 = bb.x; a01 = bb.y; a10 = bb.x; a11 = bb.y;
            }
            float v00 = tanhf(acc[mt][nt][0] + a00);
            float v01 = tanhf(acc[mt][nt][1] + a01);
            float v10 = tanhf(acc[mt][nt][2] + a10);
            float v11 = tanhf(acc[mt][nt][3] + a11);
            *reinterpret_cast<__nv_bfloat162*>(C + (size_t)row0 * NH + gcol) = __floats2bfloat162_rn(v00, v01);
            *reinterpret_cast<__nv_bfloat162*>(C + (size_t)(row0 + 8) * NH + gcol) = __floats2bfloat162_rn(v10, v11);
        }
    }
}

#define SMEMP 147456   // phase A: 4 stages x 36864 B; phase B fits (4 x 27648)

__global__ void __launch_bounds__(256)
scan_k(const float* __restrict__ ts, const float* __restrict__ noise,
       float* __restrict__ z, bf16* __restrict__ zs,
       bf16* __restrict__ hf, bf16* __restrict__ hh,
       const bf16* __restrict__ wf1z, const bf16* __restrict__ wh1,
       const bf16* __restrict__ wf2, const bf16* __restrict__ wh2,
       const float* __restrict__ hb1,
       const float* __restrict__ fb2, const float* __restrict__ hb2,
       const bf16* __restrict__ fctx,
       const float* __restrict__ diffv, float* __restrict__ dkl8,
       unsigned* flagA, unsigned* flagB)
{
    extern __shared__ char smem[];
    const int tid = threadIdx.x;
    const int cta = blockIdx.x;             // 0..127
    const int wid = tid >> 5, lane = tid & 31;
    const int lr = lane >> 2, lc = lane & 3;

    // phase A tile: 8 bm-groups x 16 bn-groups
    const int a_bm = (cta >> 4) * 128;
    const int a_bnI = cta & 15;             // <8: f, >=8: h
    const int a_grp = a_bm >> 7;            // row-group this CTA reads z / writes hf|hh

    // phase B tile: 64 x 32 (both drift and prior); 16 m-groups x 8 n-groups
    const int b_bm = (cta >> 3) * 64;
    const int b_ng = cta & 7;
    const int b_bn = b_ng * 32;
    const int b_grp = b_bm >> 7;            // row-group this CTA reads hf|hh / writes z

    // phase B smem layout (elems): Af[64*72] Ah[64*72] Bf[32*72] Bh[32*72], 4 stages
    constexpr int AF = 0, AH = 64 * 72, BF = 128 * 72, BH = 128 * 72 + 32 * 72;
    constexpr int STG2 = 192 * 72;          // 13824 elems / stage
    bf16* sm = (bf16*)smem;
    const uint32_t sbase = s2u(smem);

    for (int t = 0; t < NT - 1; t++) {
        // ---------------- phase A ----------------
        // RAW: z rows a_grp from phase B(t-1); WAR: hf|hh rows a_grp still being
        // read by phase B(t-1) consumers (they arrive only after finishing reads).
        if (t > 0) wait_flag(&flagB[(t - 1) * 8 + a_grp], 16);

        const bf16* Az = zs + (size_t)t * NL;   // rows: b, lda = NT*NL
        if (a_bnI < 8)
            gemmA(Az, wf1z, hf, fctx + (size_t)(t + 1) * NB * NH, nullptr,
                  a_bm, a_bnI * 128, smem);
        else
            gemmA(Az, wh1, hh, nullptr, hb1, a_bm, (a_bnI - 8) * 128, smem);

        arrive_flag(&flagA[t * 8 + a_grp]);

        // ---------------- phase B ----------------
        wait_flag(&flagA[t * 8 + b_grp], 16);   // hf/hh rows b_bm.. ready

        auto loadB = [&](int s, int c) {
            const int k0 = c << 6;
            uint32_t base = sbase + (uint32_t)(s * STG2) * 2u;
            #pragma unroll
            for (int i = 0; i < 2; i++) {
                int idx = tid + (i << 8);
                int m = idx >> 3, k8 = (idx & 7) << 3;
                cp16(base + (uint32_t)(AF + m * 72 + k8) * 2u, hf + (size_t)(b_bm + m) * NH + k0 + k8);
                cp16(base + (uint32_t)(AH + m * 72 + k8) * 2u, hh + (size_t)(b_bm + m) * NH + k0 + k8);
            }
            {
                int n = tid >> 3, k8 = (tid & 7) << 3;
                cp16(base + (uint32_t)(BF + n * 72 + k8) * 2u, wf2 + (size_t)(b_bn + n) * NH + k0 + k8);
                cp16(base + (uint32_t)(BH + n * 72 + k8) * 2u, wh2 + (size_t)(b_bn + n) * NH + k0 + k8);
            }
            asm volatile("cp.async.commit_group;" ::: "memory");
        };

        float ad[2][4], ap_[2][4];
        #pragma unroll
        for (int nt = 0; nt < 2; nt++)
            #pragma unroll
            for (int r = 0; r < 4; r++) { ad[nt][r] = 0.f; ap_[nt][r] = 0.f; }

        const int warpM = (wid & 3) * 16;       // 4 m-warps
        const int warpNl = (wid >> 2) * 16;     // 2 n-warps
        loadB(0, 0);
        loadB(1, 1);
        loadB(2, 2);
        for (int c = 0; c < 16; c++) {
            if (c <= 13)      asm volatile("cp.async.wait_group 2;" ::: "memory");
            else if (c == 14) asm volatile("cp.async.wait_group 1;" ::: "memory");
            else              asm volatile("cp.async.wait_group 0;" ::: "memory");
            __syncthreads();
            if (c + 3 < 16) loadB((c + 3) & 3, c + 3);

            const bf16* st = sm + (c & 3) * STG2;
            #pragma unroll
            for (int ks = 0; ks < 4; ks++) {
                const int kk = (ks << 4) + (lc << 1);
                const bf16* af = st + AF + (warpM + lr) * 72 + kk;
                uint32_t fa0 = *reinterpret_cast<const uint32_t*>(af);
                uint32_t fa1 = *reinterpret_cast<const uint32_t*>(af + 8 * 72);
                uint32_t fa2 = *reinterpret_cast<const uint32_t*>(af + 8);
                uint32_t fa3 = *reinterpret_cast<const uint32_t*>(af + 8 * 72 + 8);
                const bf16* ah = st + AH + (warpM + lr) * 72 + kk;
                uint32_t ha0 = *reinterpret_cast<const uint32_t*>(ah);
                uint32_t ha1 = *reinterpret_cast<const uint32_t*>(ah + 8 * 72);
                uint32_t ha2 = *reinterpret_cast<const uint32_t*>(ah + 8);
                uint32_t ha3 = *reinterpret_cast<const uint32_t*>(ah + 8 * 72 + 8);
                #pragma unroll
                for (int nt = 0; nt < 2; nt++) {
                    const bf16* bf_ = st + BF + (warpNl + nt * 8 + lr) * 72 + kk;
                    uint32_t b0 = *reinterpret_cast<const uint32_t*>(bf_);
                    uint32_t b1 = *reinterpret_cast<const uint32_t*>(bf_ + 8);
                    mma_bf16(ad[nt], fa0, fa1, fa2, fa3, b0, b1);
                    const bf16* bh_ = st + BH + (warpNl + nt * 8 + lr) * 72 + kk;
                    uint32_t c0 = *reinterpret_cast<const uint32_t*>(bh_);
                    uint32_t c1 = *reinterpret_cast<const uint32_t*>(bh_ + 8);
                    mma_bf16(ap_[nt], ha0, ha1, ha2, ha3, c0, c1);
                }
            }
        }

        // ---- fused step update ----
        const float dt = ts[t + 1] - ts[t];
        const float sq = sqrtf(dt);
        float* sred = (float*)smem;             // stage-0 area, retired
        float pr_lo = 0.f, pr_hi = 0.f;

        #pragma unroll
        for (int nt = 0; nt < 2; nt++) {
            const int col = b_bn + warpNl + nt * 8 + (lc << 1);
            const float fb0 = fb2[col], fb1v = fb2[col + 1];
            const float hb0 = hb2[col], hb1v = hb2[col + 1];
            float d00 = ad[nt][0] + fb0, d01 = ad[nt][1] + fb1v;
            float d10 = ad[nt][2] + fb0, d11 = ad[nt][3] + fb1v;
            float p00 = ap_[nt][0] + hb0, p01 = ap_[nt][1] + hb1v;
            float p10 = ap_[nt][2] + hb0, p11 = ap_[nt][3] + hb1v;

            const float df0 = diffv[col], df1 = diffv[col + 1];
            float den0 = fabsf(df0) > EPSV ? df0 : ((df0 > 0.f) - (df0 < 0.f)) * EPSV;
            float den1 = fabsf(df1) > EPSV ? df1 : ((df1 > 0.f) - (df1 < 0.f)) * EPSV;
            float r00 = (d00 - p00) / den0, r01 = (d01 - p01) / den1;
            float r10 = (d10 - p10) / den0, r11 = (d11 - p11) / den1;
            pr_lo += r00 * r00 + r01 * r01;
            pr_hi += r10 * r10 + r11 * r11;

            const int b0r = b_bm + warpM + lr, b1r = b0r + 8;
            {
                size_t zi = (size_t)b0r * NL + col;
                float e0 = noise[((size_t)t * NB + b0r) * NL + col];
                float e1 = noise[((size_t)t * NB + b0r) * NL + col + 1];
                float zn0 = z[zi] + d00 * dt + df0 * sq * e0;
                float zn1 = z[zi + 1] + d01 * dt + df1 * sq * e1;
                z[zi] = zn0; z[zi + 1] = zn1;
                *reinterpret_cast<__nv_bfloat162*>(zs + ((size_t)b0r * NT + t + 1) * NL + col)
                    = __floats2bfloat162_rn(zn0, zn1);
            }
            {
                size_t zi = (size_t)b1r * NL + col;
                float e0 = noise[((size_t)t * NB + b1r) * NL + col];
                float e1 = noise[((size_t)t * NB + b1r) * NL + col + 1];
                float zn0 = z[zi] + d10 * dt + df0 * sq * e0;
                float zn1 = z[zi + 1] + d11 * dt + df1 * sq * e1;
                z[zi] = zn0; z[zi + 1] = zn1;
                *reinterpret_cast<__nv_bfloat162*>(zs + ((size_t)b1r * NT + t + 1) * NL + col)
                    = __floats2bfloat162_rn(zn0, zn1);
            }
        }

        // row-rate reduction: shuffle over lc (lanes differ in bits 0..1)
        pr_lo += __shfl_xor_sync(0xffffffff, pr_lo, 1);
        pr_lo += __shfl_xor_sync(0xffffffff, pr_lo, 2);
        pr_hi += __shfl_xor_sync(0xffffffff, pr_hi, 1);
        pr_hi += __shfl_xor_sync(0xffffffff, pr_hi, 2);
        const int ngrp = wid >> 2;
        __syncthreads();   // all warps past chunk-15 compute before stage-0 reuse
        if (lc == 0) {
            sred[(warpM + lr) * 2 + ngrp] = pr_lo;
            sred[(warpM + lr + 8) * 2 + ngrp] = pr_hi;
        }
        __syncthreads();
        if (tid < 64)
            dkl8[b_ng * NB + b_bm + tid] += (sred[tid * 2] + sred[tid * 2 + 1]) * dt;

        // arrive AFTER hf/hh reads done + z/zs stores done (covers RAW + WAR)
        arrive_flag(&flagB[t * 8 + b_grp]);
    }
}

// ---------------- prologue kernels --------------------------------------------
__global__ void transp_k(const float* __restrict__ W, bf16* __restrict__ Wt, int K, int N) {
    __shared__ float t[32][33];
    int n0 = blockIdx.x * 32, k0 = blockIdx.y * 32;
    int tx = threadIdx.x, ty = threadIdx.y;  // 32 x 8
    #pragma unroll
    for (int j = 0; j < 4; j++)
        t[ty + j * 8][tx] = W[(size_t)(k0 + ty + j * 8) * N + n0 + tx];
    __syncthreads();
    #pragma unroll
    for (int j = 0; j < 4; j++)
        Wt[(size_t)(n0 + ty + j * 8) * K + k0 + tx] = __float2bfloat16(t[tx][ty + j * 8]);
}

__global__ void copy_xs_k(const float* __restrict__ xs, bf16* __restrict__ ctx,
                          bf16* __restrict__ xst) {
    size_t i = (size_t)blockIdx.x * 256 + threadIdx.x;
    size_t bt = i >> 8, d = i & 255;
    bf16 v = __float2bfloat16(xs[i]);
    ctx[bt * 512 + 256 + d] = v;
    xst[i] = v;
}

__global__ void diffv_k(const float* __restrict__ gamma, float* __restrict__ diffv) {
    int l = threadIdx.x;
    diffv[l] = sqrtf(2.f / (BETAV * gamma[l]));
}

__global__ void z0_k(const float* __restrict__ q, const float* __restrict__ eps0,
                     const float* __restrict__ pm, const float* __restrict__ pl,
                     float* __restrict__ z, bf16* __restrict__ zs,
                     float* __restrict__ kl0, float* __restrict__ dkl8,
                     unsigned* __restrict__ flagA, unsigned* __restrict__ flagB)
{
    __shared__ float sh[256];
    int b = blockIdx.x, l = threadIdx.x;
    if (b == 0) {
        #pragma unroll
        for (int i = 0; i < 32; i++) dkl8[l + i * 256] = 0.f;
        #pragma unroll
        for (int i = 0; i < 2; i++) {
            flagA[l + i * 256] = 0u;
            flagB[l + i * 256] = 0u;
        }
    }
    float qm = q[b * 512 + l];
    float ql = q[b * 512 + 256 + l];
    float z0 = qm + expf(ql) * eps0[b * NL + l];
    z[b * NL + l] = z0;
    zs[(size_t)b * NT * NL + l] = __float2bfloat16(z0);
    float pmv = pm[l], plv = pl[l];
    float dm = qm - pmv;
    float term = plv - ql + (expf(2.f * ql) + dm * dm) / (2.f * expf(2.f * plv)) - 0.5f;
    float s = block_reduce_sum_256(term, sh);
    if (l == 0) kl0[b] = s;
}

__global__ void finalize_k(const float* __restrict__ partials, int np,
                           const float* __restrict__ dkl8, const float* __restrict__ kl0,
                           const float* __restrict__ nstd_p, float* __restrict__ out)
{
    __shared__ float sh[256];
    int tid = threadIdx.x;
    float s = 0.f;
    for (int i = tid; i < np; i += 256) s += partials[i];
    float tot = block_reduce_sum_256(s, sh);

    float s2 = 0.f;
    for (int i = tid; i < 8 * NB; i += 256) s2 += dkl8[i];
    float dkl_tot = block_reduce_sum_256(s2, sh);

    float s3 = 0.f;
    for (int i = tid; i < NB; i += 256) s3 += kl0[i];
    float kl0_tot = block_reduce_sum_256(s3, sh);

    if (tid == 0) {
        float nstd = nstd_p[0];
        float cst = (float)NT * (float)ND * (-logf(nstd) - 0.5f * LOG2PI);
        float log_pxs = tot / (float)NB + cst;
        out[0] = -log_pxs;
        out[1] = dkl_tot / (float)NB + kl0_tot / (float)NB;
    }
}

// ---------------- launch ------------------------------------------------------
#define SMEM128 (2 * (128*72 + 128*72) * 2)   // 73728

extern "C" void kernel_launch(void* const* d_in, const int* in_sizes, int n_in,
                              void* d_out, int out_size)
{
    const float* xs        = (const float*)d_in[0];
    const float* ts        = (const float*)d_in[1];
    const float* noise_std = (const float*)d_in[2];
    const float* eps0      = (const float*)d_in[3];
    const float* noise     = (const float*)d_in[4];
    const float* enc_w1    = (const float*)d_in[5];
    const float* enc_b1    = (const float*)d_in[6];
    const float* enc_w2    = (const float*)d_in[7];
    const float* enc_b2    = (const float*)d_in[8];
    const float* qz0_w     = (const float*)d_in[9];
    const float* qz0_b     = (const float*)d_in[10];
    const float* f_w1      = (const float*)d_in[11];
    const float* f_b1      = (const float*)d_in[12];
    const float* f_w2      = (const float*)d_in[13];
    const float* f_b2      = (const float*)d_in[14];
    const float* h_w1      = (const float*)d_in[15];
    const float* h_b1      = (const float*)d_in[16];
    const float* h_w2      = (const float*)d_in[17];
    const float* h_b2      = (const float*)d_in[18];
    const float* proj_w    = (const float*)d_in[19];
    const float* proj_b    = (const float*)d_in[20];
    const float* pz0_mean  = (const float*)d_in[21];
    const float* pz0_logstd= (const float*)d_in[22];
    const float* gamma     = (const float*)d_in[23];

    bf16 *y1, *ctx, *xst, *zs, *hf, *hh, *wtb, *fctx;
    float *z, *q, *dkl8, *kl0, *diffv, *partials;
    unsigned *flagA, *flagB;
    cudaGetSymbolAddress((void**)&y1, g_y1);
    cudaGetSymbolAddress((void**)&ctx, g_ctx);
    cudaGetSymbolAddress((void**)&xst, g_xst);
    cudaGetSymbolAddress((void**)&zs, g_zs);
    cudaGetSymbolAddress((void**)&z, g_z);
    cudaGetSymbolAddress((void**)&hf, g_hf);
    cudaGetSymbolAddress((void**)&hh, g_hh);
    cudaGetSymbolAddress((void**)&q, g_q);
    cudaGetSymbolAddress((void**)&fctx, g_fctx);
    cudaGetSymbolAddress((void**)&wtb, g_wtb);
    cudaGetSymbolAddress((void**)&dkl8, g_dkl8);
    cudaGetSymbolAddress((void**)&kl0, g_kl0);
    cudaGetSymbolAddress((void**)&diffv, g_diffv);
    cudaGetSymbolAddress((void**)&partials, g_partials);
    cudaGetSymbolAddress((void**)&flagA, g_flagA);
    cudaGetSymbolAddress((void**)&flagB, g_flagB);

    cudaFuncSetAttribute(gemm_bf<128,1,1,0,0>, cudaFuncAttributeMaxDynamicSharedMemorySize, SMEM128);
    cudaFuncSetAttribute(gemm_bf<128,0,1,0,0>, cudaFuncAttributeMaxDynamicSharedMemorySize, SMEM128);
    cudaFuncSetAttribute(gemm_bf<128,0,0,0,0>, cudaFuncAttributeMaxDynamicSharedMemorySize, SMEM128);
    cudaFuncSetAttribute(gemm_bf<128,0,0,1,0>, cudaFuncAttributeMaxDynamicSharedMemorySize, SMEM128);
    cudaFuncSetAttribute(gemm_bf<128,0,0,0,1>, cudaFuncAttributeMaxDynamicSharedMemorySize, SMEM128);
    cudaFuncSetAttribute(scan_k, cudaFuncAttributeMaxDynamicSharedMemorySize, SMEMP);

    const int M = NB * NT;
    dim3 tb(32, 8);

    // ---- weights: transpose + bf16 ----
    transp_k<<<dim3(NH/32,  ND/32), tb>>>(enc_w1, wtb + W_ENC1, ND,  NH);
    transp_k<<<dim3(NL/32,  NH/32), tb>>>(enc_w2, wtb + W_ENC2, NH,  NL);
    transp_k<<<dim3(512/32, 512/32),tb>>>(qz0_w,  wtb + W_QZ0,  512, 512);
    transp_k<<<dim3(NH/32,  256/32),tb>>>(f_w1,            wtb + W_F1Z, 256, NH);
    transp_k<<<dim3(NH/32,  512/32),tb>>>(f_w1 + 256 * NH, wtb + W_F1C, 512, NH);
    transp_k<<<dim3(NL/32,  NH/32), tb>>>(f_w2,   wtb + W_F2,   NH,  NL);
    transp_k<<<dim3(NH/32,  NL/32), tb>>>(h_w1,   wtb + W_H1,   NL,  NH);
    transp_k<<<dim3(NL/32,  NH/32), tb>>>(h_w2,   wtb + W_H2,   NH,  NL);
    transp_k<<<dim3(ND/32,  NL/32), tb>>>(proj_w, wtb + W_PROJ, NL,  ND);
    copy_xs_k<<<(int)((size_t)M * ND / 256), 256>>>(xs, ctx, xst);

    GArgs zg{};

    // ---- encoder ----
    {
        GArgs a{xst, ND, wtb + W_ENC1, enc_b1, y1, NH, ND};
        gemm_bf<128,1,1,0,0><<<dim3(NH/128, M/128), 256, SMEM128>>>(a, a, M/128, nullptr, nullptr, nullptr);
    }
    {
        GArgs a{y1, NH, wtb + W_ENC2, enc_b2, ctx, 512, NH};
        gemm_bf<128,0,1,0,0><<<dim3(NL/128, M/128), 256, SMEM128>>>(a, a, M/128, nullptr, nullptr, nullptr);
    }

    // ---- fctx[t][b][:] = ctx[b][t][:] @ f_w1[256:768] + f_b1 (bf16, t-scatter) ----
    {
        GArgs a{ctx, 512, wtb + W_F1C, f_b1, fctx, NH, 512};
        gemm_bf<128,0,0,0,1><<<dim3(NH/128, M/128), 256, SMEM128>>>(a, a, M/128, nullptr, nullptr, nullptr);
    }

    // ---- q = ctx[:,0,:] @ qz0_w + qz0_b ----
    {
        GArgs a{ctx, NT * 512, wtb + W_QZ0, qz0_b, q, 512, 512};
        gemm_bf<128,0,0,0,0><<<dim3(512/128, NB/128), 256, SMEM128>>>(a, a, NB/128, nullptr, nullptr, nullptr);
    }

    z0_k<<<NB, 256>>>(q, eps0, pz0_mean, pz0_logstd, z, zs, kl0, dkl8, flagA, flagB);
    diffv_k<<<1, NL>>>(gamma, diffv);

    // ---- persistent scan: dataflow flags, no global barriers ----
    scan_k<<<128, 256, SMEMP>>>(ts, noise, z, zs, hf, hh,
                                wtb + W_F1Z, wtb + W_H1, wtb + W_F2, wtb + W_H2,
                                h_b1, f_b2, h_b2, fctx, diffv, dkl8, flagA, flagB);

    // ---- decoder fused with NLL reduction ----
    {
        GArgs a{zs, NL, wtb + W_PROJ, proj_b, nullptr, ND, NL};
        gemm_bf<128,0,0,1,0><<<dim3(ND/128, M/128), 256, SMEM128>>>(a, zg, M/128, xs, noise_std, partials);
    }

    finalize_k<<<1, 256>>>(partials, (M/128) * (ND/128), dkl8, kl0, noise_std, (float*)d_out);

    (void)in_sizes; (void)n_in; (void)out_size;
}

// round 13
// speedup vs baseline: 1.0149x; 1.0005x over previous
#include <cuda_runtime.h>
#include <cuda_bf16.h>
#include <math.h>
#include <stdint.h>

// ---------------- problem dims ------------------------------------------------
#define NB 1024
#define NT 64
#define ND 256
#define NL 256
#define NH 1024
#define EPSV 1e-7f
#define LOG2PI 1.8378770664093453f
#define BETAV (1.0f/3.0f)

typedef __nv_bfloat16 bf16;

// ---------------- scratch (device globals) ------------------------------------
__device__ __align__(16) bf16  g_y1[(size_t)NB * NT * NH];
__device__ __align__(16) bf16  g_ctx[(size_t)NB * NT * 512];
__device__ __align__(16) bf16  g_xst[(size_t)NB * NT * ND];
__device__ __align__(16) bf16  g_zs[(size_t)NB * NT * NL];
__device__ __align__(16) float g_z[NB * NL];
__device__ __align__(16) bf16  g_hf[NB * NH];
__device__ __align__(16) bf16  g_hh[NB * NH];
__device__ __align__(16) float g_q[NB * 512];
__device__ __align__(16) bf16  g_fctx[(size_t)NT * NB * NH];   // [t][b][1024] bf16
__device__ __align__(16) bf16  g_wtb[2424832];
__device__ float g_dkl8[8 * NB];
__device__ float g_kl0[NB];
__device__ float g_partials[4096];
__device__ unsigned g_flagA[NT * 8];   // phase-A done counters per (t, row-group)
__device__ unsigned g_flagB[NT * 8];   // phase-B done (t<63); slots 504..511 = z0-done

// weight offsets in g_wtb (elements), stored transposed [N][K]
#define W_ENC1 0
#define W_ENC2 262144
#define W_QZ0  524288
#define W_F1Z  786432
#define W_F1C  1048576
#define W_F2   1572864
#define W_H1   1835008
#define W_H2   2097152
#define W_PROJ 2359296

// ---------------- helpers -----------------------------------------------------
__device__ __forceinline__ uint32_t s2u(const void* p) {
    uint32_t a;
    asm("{ .reg .u64 t; cvta.to.shared.u64 t, %1; cvt.u32.u64 %0, t; }" : "=r"(a) : "l"(p));
    return a;
}
__device__ __forceinline__ void cp16(uint32_t saddr, const void* g) {
    asm volatile("cp.async.cg.shared.global [%0], [%1], 16;" :: "r"(saddr), "l"(g));
}
__device__ __forceinline__ void mma_bf16(float* c, uint32_t a0, uint32_t a1, uint32_t a2, uint32_t a3,
                                         uint32_t b0, uint32_t b1) {
    asm volatile("mma.sync.aligned.m16n8k16.row.col.f32.bf16.bf16.f32 "
                 "{%0,%1,%2,%3},{%4,%5,%6,%7},{%8,%9},{%0,%1,%2,%3};"
                 : "+f"(c[0]), "+f"(c[1]), "+f"(c[2]), "+f"(c[3])
                 : "r"(a0), "r"(a1), "r"(a2), "r"(a3), "r"(b0), "r"(b1));
}
__device__ __forceinline__ float block_reduce_sum_256(float v, float* sh) {
    int tid = threadIdx.x;
    sh[tid] = v;
    __syncthreads();
    #pragma unroll
    for (int s = 128; s > 0; s >>= 1) {
        if (tid < s) sh[tid] += sh[tid + s];
        __syncthreads();
    }
    float r = sh[0];
    __syncthreads();
    return r;
}
__device__ __forceinline__ void wait_flag(unsigned* f, unsigned tgt) {
    if (threadIdx.x == 0) {
        unsigned v;
        do {
            asm volatile("ld.acquire.gpu.u32 %0, [%1];" : "=r"(v) : "l"(f) : "memory");
        } while (v < tgt);
    }
    __syncthreads();
}
__device__ __forceinline__ void arrive_flag(unsigned* f) {
    __syncthreads();
    if (threadIdx.x == 0)
        asm volatile("red.release.gpu.add.u32 [%0], 1;" :: "l"(f) : "memory");
}

// ---------------- standalone bf16 GEMM ----------------------------------------
struct GArgs {
    const bf16* A; int lda;
    const bf16* W;
    const float* bias;
    void* C; int ldc;
    int K;
};

template<int BMT, int ACT, int OUTBF, int EPI, int TSCAT>
__global__ void __launch_bounds__(256)
gemm_bf(GArgs g0, GArgs g1, int mSplit,
        const float* __restrict__ xs, const float* __restrict__ nstd_p,
        float* __restrict__ partials)
{
    extern __shared__ char smem[];
    constexpr int MT  = (BMT + 31) / 32;
    constexpr int ASZ = BMT * 72;
    constexpr int BSZ = 128 * 72;
    constexpr int STG = ASZ + BSZ;

    const int tid  = threadIdx.x;
    const int wid  = tid >> 5;
    const int lane = tid & 31;
    const int lr   = lane >> 2;
    const int lc   = lane & 3;

    const bool grp1 = ((int)blockIdx.y >= mSplit);
    const GArgs g = grp1 ? g1 : g0;
    const int bm = (grp1 ? ((int)blockIdx.y - mSplit) : (int)blockIdx.y) * BMT;
    const int bn = (int)blockIdx.x * 128;

    bf16* sm = (bf16*)smem;
    const uint32_t sbase = s2u(smem);
    const int warpM = (wid >> 2) * (BMT / 2);
    const int warpN = (wid & 3) * 32;

    auto loadtile = [&](int s, int c) {
        const int k0 = c << 6;
        uint32_t sA = sbase + (uint32_t)(s * STG) * 2u;
        uint32_t sB = sA + (uint32_t)ASZ * 2u;
        const bf16* Ag = g.A + (size_t)bm * g.lda + k0;
        #pragma unroll
        for (int i = 0; i < BMT / 32; i++) {
            int idx = tid + (i << 8);
            int m = idx >> 3, k8 = (idx & 7) << 3;
            cp16(sA + (uint32_t)(m * 72 + k8) * 2u, Ag + (size_t)m * g.lda + k8);
        }
        const bf16* Wg = g.W + (size_t)bn * g.K + k0;
        #pragma unroll
        for (int i = 0; i < 4; i++) {
            int idx = tid + (i << 8);
            int n = idx >> 3, k8 = (idx & 7) << 3;
            cp16(sB + (uint32_t)(n * 72 + k8) * 2u, Wg + (size_t)n * g.K + k8);
        }
        asm volatile("cp.async.commit_group;" ::: "memory");
    };

    float acc[MT][4][4];
    #pragma unroll
    for (int mt = 0; mt < MT; mt++)
        #pragma unroll
        for (int nt = 0; nt < 4; nt++)
            #pragma unroll
            for (int r = 0; r < 4; r++) acc[mt][nt][r] = 0.f;

    const int nch = g.K >> 6;
    loadtile(0, 0);
    if (nch > 1) loadtile(1, 1);

    for (int c = 0; c < nch; c++) {
        if (c + 1 < nch) asm volatile("cp.async.wait_group 1;" ::: "memory");
        else             asm volatile("cp.async.wait_group 0;" ::: "memory");
        __syncthreads();
        const bf16* As = sm + (c & 1) * STG;
        const bf16* Bs = As + ASZ;
        #pragma unroll
        for (int ks = 0; ks < 4; ks++) {
            const int kk = (ks << 4) + (lc << 1);
            uint32_t b[4][2];
            #pragma unroll
            for (int nt = 0; nt < 4; nt++) {
                const bf16* bp = Bs + (warpN + nt * 8 + lr) * 72 + kk;
                b[nt][0] = *reinterpret_cast<const uint32_t*>(bp);
                b[nt][1] = *reinterpret_cast<const uint32_t*>(bp + 8);
            }
            #pragma unroll
            for (int mt = 0; mt < MT; mt++) {
                const bf16* ap = As + (warpM + mt * 16 + lr) * 72 + kk;
                uint32_t a0 = *reinterpret_cast<const uint32_t*>(ap);
                uint32_t a1 = *reinterpret_cast<const uint32_t*>(ap + 8 * 72);
                uint32_t a2 = *reinterpret_cast<const uint32_t*>(ap + 8);
                uint32_t a3 = *reinterpret_cast<const uint32_t*>(ap + 8 * 72 + 8);
                #pragma unroll
                for (int nt = 0; nt < 4; nt++)
                    mma_bf16(acc[mt][nt], a0, a1, a2, a3, b[nt][0], b[nt][1]);
            }
        }
        __syncthreads();
        if (c + 2 < nch) loadtile(c & 1, c + 2);
    }

    float loc = 0.f;
    const float invs = EPI ? (1.f / nstd_p[0]) : 0.f;
    #pragma unroll
    for (int mt = 0; mt < MT; mt++) {
        const int row0 = bm + warpM + mt * 16 + lr;
        #pragma unroll
        for (int nt = 0; nt < 4; nt++) {
            const int col = bn + warpN + nt * 8 + (lc << 1);
            float2 bb = *reinterpret_cast<const float2*>(g.bias + col);
            float v00 = acc[mt][nt][0] + bb.x;
            float v01 = acc[mt][nt][1] + bb.y;
            float v10 = acc[mt][nt][2] + bb.x;
            float v11 = acc[mt][nt][3] + bb.y;
            if (ACT) { v00 = tanhf(v00); v01 = tanhf(v01); v10 = tanhf(v10); v11 = tanhf(v11); }
            if (EPI) {
                float2 x0 = *reinterpret_cast<const float2*>(xs + (size_t)row0 * g.ldc + col);
                float2 x1 = *reinterpret_cast<const float2*>(xs + (size_t)(row0 + 8) * g.ldc + col);
                float r0 = (x0.x - v00) * invs, r1 = (x0.y - v01) * invs;
                float r2 = (x1.x - v10) * invs, r3 = (x1.y - v11) * invs;
                loc += r0 * r0 + r1 * r1 + r2 * r2 + r3 * r3;
            } else if (TSCAT) {
                bf16* Cb = (bf16*)g.C;
                size_t o0 = ((size_t)(row0 & 63) * NB + (row0 >> 6)) * NH + col;
                int row1 = row0 + 8;
                size_t o1 = ((size_t)(row1 & 63) * NB + (row1 >> 6)) * NH + col;
                *reinterpret_cast<__nv_bfloat162*>(Cb + o0) = __floats2bfloat162_rn(v00, v01);
                *reinterpret_cast<__nv_bfloat162*>(Cb + o1) = __floats2bfloat162_rn(v10, v11);
            } else if (OUTBF) {
                bf16* Cb = (bf16*)g.C;
                *reinterpret_cast<__nv_bfloat162*>(Cb + (size_t)row0 * g.ldc + col) = __floats2bfloat162_rn(v00, v01);
                *reinterpret_cast<__nv_bfloat162*>(Cb + (size_t)(row0 + 8) * g.ldc + col) = __floats2bfloat162_rn(v10, v11);
            } else {
                float* Cf = (float*)g.C;
                *reinterpret_cast<float2*>(Cf + (size_t)row0 * g.ldc + col) = make_float2(v00, v01);
                *reinterpret_cast<float2*>(Cf + (size_t)(row0 + 8) * g.ldc + col) = make_float2(v10, v11);
            }
        }
    }
    if (EPI) {
        __syncthreads();
        float tot = block_reduce_sum_256(loc, (float*)smem);
        if (tid == 0) partials[blockIdx.y * gridDim.x + blockIdx.x] = -0.5f * tot;
    }
}

// ---------------- fused prologue: transposes + xs copy + resets ----------------
struct PrepArgs {
    const float* src[9];
    int off[9];
    int K[9], N[9];
    int tileOff[10];
    const float* xs;
};

__global__ void __launch_bounds__(256)
prep_k(PrepArgs pa, bf16* __restrict__ wtb, bf16* __restrict__ ctx, bf16* __restrict__ xst,
       float* __restrict__ dkl8, unsigned* __restrict__ flagA, unsigned* __restrict__ flagB)
{
    __shared__ float t[32][33];
    const int bx = blockIdx.x;
    const int tid = threadIdx.x;

    if (bx == 0) {   // per-replay resets (stream-ordered before scan_k)
        #pragma unroll
        for (int i = 0; i < 32; i++) dkl8[tid + i * 256] = 0.f;
        #pragma unroll
        for (int i = 0; i < 2; i++) {
            flagA[tid + i * 256] = 0u;
            flagB[tid + i * 256] = 0u;
        }
    }

    if (bx < pa.tileOff[9]) {
        // weight transpose tile
        int m = 0;
        #pragma unroll
        for (int i = 1; i < 9; i++) if (bx >= pa.tileOff[i]) m = i;
        const int local = bx - pa.tileOff[m];
        const int K = pa.K[m], N = pa.N[m];
        const int nTiles = N >> 5;
        const int n0 = (local % nTiles) << 5;
        const int k0 = (local / nTiles) << 5;
        const float* W = pa.src[m];
        bf16* Wt = wtb + pa.off[m];
        const int tx = tid & 31, ty = tid >> 5;   // 32 x 8
        #pragma unroll
        for (int j = 0; j < 4; j++)
            t[ty + j * 8][tx] = W[(size_t)(k0 + ty + j * 8) * N + n0 + tx];
        __syncthreads();
        #pragma unroll
        for (int j = 0; j < 4; j++)
            Wt[(size_t)(n0 + ty + j * 8) * K + k0 + tx] = __float2bfloat16(t[tx][ty + j * 8]);
    } else {
        // xs copy: 1024 elems per block, 4 per thread (vectorized load)
        size_t i0 = ((size_t)(bx - pa.tileOff[9]) << 10) + ((size_t)tid << 2);
        float4 v = *reinterpret_cast<const float4*>(pa.xs + i0);
        float vv[4] = {v.x, v.y, v.z, v.w};
        #pragma unroll
        for (int u = 0; u < 4; u++) {
            size_t idx = i0 + u;
            size_t bt = idx >> 8, d = idx & 255;
            bf16 b = __float2bfloat16(vv[u]);
            ctx[bt * 512 + 256 + d] = b;
            xst[idx] = b;
        }
    }
}

// ---------------- persistent scan ---------------------------------------------
__device__ void gemmA(const bf16* A, const bf16* W, bf16* C,
                      const bf16* fadd, const float* bias,
                      int bm, int bn, char* smem)
{
    constexpr int lda = NT * NL;
    constexpr int ASZ = 128 * 72, STG = 2 * 128 * 72;
    const int tid = threadIdx.x;
    const int wid = tid >> 5, lane = tid & 31;
    const int lr = lane >> 2, lc = lane & 3;
    bf16* sm = (bf16*)smem;
    const uint32_t sbase = s2u(smem);
    const int warpM = (wid >> 2) * 64;
    const int warpN = (wid & 3) * 32;

    auto loadtile = [&](int s, int c) {
        const int k0 = c << 6;
        uint32_t sA = sbase + (uint32_t)(s * STG) * 2u;
        uint32_t sB = sA + (uint32_t)ASZ * 2u;
        #pragma unroll
        for (int i = 0; i < 4; i++) {
            int idx = tid + (i << 8);
            int m = idx >> 3, k8 = (idx & 7) << 3;
            cp16(sA + (uint32_t)(m * 72 + k8) * 2u, A + (size_t)(bm + m) * lda + k0 + k8);
        }
        #pragma unroll
        for (int i = 0; i < 4; i++) {
            int idx = tid + (i << 8);
            int n = idx >> 3, k8 = (idx & 7) << 3;
            cp16(sB + (uint32_t)(n * 72 + k8) * 2u, W + (size_t)(bn + n) * 256 + k0 + k8);
        }
        asm volatile("cp.async.commit_group;" ::: "memory");
    };

    float acc[4][4][4];
    #pragma unroll
    for (int mt = 0; mt < 4; mt++)
        #pragma unroll
        for (int nt = 0; nt < 4; nt++)
            #pragma unroll
            for (int r = 0; r < 4; r++) acc[mt][nt][r] = 0.f;

    loadtile(0, 0);
    loadtile(1, 1);
    loadtile(2, 2);
    for (int c = 0; c < 4; c++) {
        if (c <= 1)      asm volatile("cp.async.wait_group 2;" ::: "memory");
        else if (c == 2) asm volatile("cp.async.wait_group 1;" ::: "memory");
        else             asm volatile("cp.async.wait_group 0;" ::: "memory");
        __syncthreads();
        if (c + 3 < 4) loadtile(c + 3, c + 3);

        const bf16* As = sm + c * STG;
        const bf16* Bs = As + ASZ;
        #pragma unroll
        for (int ks = 0; ks < 4; ks++) {
            const int kk = (ks << 4) + (lc << 1);
            uint32_t b[4][2];
            #pragma unroll
            for (int nt = 0; nt < 4; nt++) {
                const bf16* bp = Bs + (warpN + nt * 8 + lr) * 72 + kk;
                b[nt][0] = *reinterpret_cast<const uint32_t*>(bp);
                b[nt][1] = *reinterpret_cast<const uint32_t*>(bp + 8);
            }
            #pragma unroll
            for (int mt = 0; mt < 4; mt++) {
                const bf16* ap = As + (warpM + mt * 16 + lr) * 72 + kk;
                uint32_t a0 = *reinterpret_cast<const uint32_t*>(ap);
                uint32_t a1 = *reinterpret_cast<const uint32_t*>(ap + 8 * 72);
                uint32_t a2 = *reinterpret_cast<const uint32_t*>(ap + 8);
                uint32_t a3 = *reinterpret_cast<const uint32_t*>(ap + 8 * 72 + 8);
                #pragma unroll
                for (int nt = 0; nt < 4; nt++)
                    mma_bf16(acc[mt][nt], a0, a1, a2, a3, b[nt][0], b[nt][1]);
            }
        }
    }

    #pragma unroll
    for (int mt = 0; mt < 4; mt++) {
        const int row0 = bm + warpM + mt * 16 + lr;
        #pragma unroll
        for (int nt = 0; nt < 4; nt++) {
            const int gcol = bn + warpN + nt * 8 + (lc << 1);
            float a00, a01, a10, a11;
            if (fadd) {
                __nv_bfloat162 f0 = *reinterpret_cast<const __nv_bfloat162*>(fadd + (size_t)row0 * NH + gcol);
                __nv_bfloat162 f1 = *reinterpret_cast<const __nv_bfloat162*>(fadd + (size_t)(row0 + 8) * NH + gcol);
                a00 = __low2float(f0); a01 = __high2float(f0);
                a10 = __low2float(f1); a11 = __high2float(f1);
            } else {
                float2 bb = *reinterpret_cast<const float2*>(bias + gcol);
                a00 = bb.x; a01 = bb.y; a10 = bb.x; a11 = bb.y;
            }
            float v00 = tanhf(acc[mt][nt][0] + a00);
            float v01 = tanhf(acc[mt][nt][1] + a01);
            float v10 = tanhf(acc[mt][nt][2] + a10);
            float v11 = tanhf(acc[mt][nt][3] + a11);
            *reinterpret_cast<__nv_bfloat162*>(C + (size_t)row0 * NH + gcol) = __floats2bfloat162_rn(v00, v01);
            *reinterpret_cast<__nv_bfloat162*>(C + (size_t)(row0 + 8) * NH + gcol) = __floats2bfloat162_rn(v10, v11);
        }
    }
}

#define SMEMP 147456

__global__ void __launch_bounds__(256)
scan_k(const float* __restrict__ ts, const float* __restrict__ noise,
       float* __restrict__ z, bf16* __restrict__ zs,
       bf16* __restrict__ hf, bf16* __restrict__ hh,
       const bf16* __restrict__ wf1z, const bf16* __restrict__ wh1,
       const bf16* __restrict__ wf2, const bf16* __restrict__ wh2,
       const float* __restrict__ hb1,
       const float* __restrict__ fb2, const float* __restrict__ hb2,
       const bf16* __restrict__ fctx,
       const float* __restrict__ gamma, float* __restrict__ dkl8,
       unsigned* flagA, unsigned* flagB,
       const float* __restrict__ q, const float* __restrict__ eps0,
       const float* __restrict__ pm, const float* __restrict__ pl,
       float* __restrict__ kl0)
{
    extern __shared__ char smem[];
    const int tid = threadIdx.x;
    const int cta = blockIdx.x;             // 0..127
    const int wid = tid >> 5, lane = tid & 31;
    const int lr = lane >> 2, lc = lane & 3;

    // ---- fused z0 prologue: CTA c handles b rows [8c, 8c+8), one per warp ----
    {
        const int b = cta * 8 + wid;
        float part = 0.f;
        #pragma unroll
        for (int j = 0; j < 8; j++) {
            const int l = lane + j * 32;
            float qm = q[b * 512 + l];
            float ql = q[b * 512 + 256 + l];
            float z0 = qm + expf(ql) * eps0[b * NL + l];
            z[b * NL + l] = z0;
            zs[(size_t)b * NT * NL + l] = __float2bfloat16(z0);
            float pmv = pm[l], plv = pl[l];
            float dm = qm - pmv;
            part += plv - ql + (expf(2.f * ql) + dm * dm) / (2.f * expf(2.f * plv)) - 0.5f;
        }
        #pragma unroll
        for (int s = 16; s > 0; s >>= 1) part += __shfl_xor_sync(0xffffffff, part, s);
        if (lane == 0) kl0[b] = part;
    }
    arrive_flag(&flagB[504 + (cta >> 4)]);   // z0 rows of group (cta>>4) done

    // phase A tile: 8 bm-groups x 16 bn-groups
    const int a_bm = (cta >> 4) * 128;
    const int a_bnI = cta & 15;
    const int a_grp = a_bm >> 7;

    // phase B tile: 64 x 32; 16 m-groups x 8 n-groups
    const int b_bm = (cta >> 3) * 64;
    const int b_ng = cta & 7;
    const int b_bn = b_ng * 32;
    const int b_grp = b_bm >> 7;

    constexpr int AF = 0, AH = 64 * 72, BF = 128 * 72, BH = 128 * 72 + 32 * 72;
    constexpr int STG2 = 192 * 72;
    bf16* sm = (bf16*)smem;
    const uint32_t sbase = s2u(smem);

    for (int t = 0; t < NT - 1; t++) {
        // ---------------- phase A ----------------
        wait_flag(&flagB[(t == 0) ? (504 + a_grp) : ((t - 1) * 8 + a_grp)], 16);

        const bf16* Az = zs + (size_t)t * NL;
        if (a_bnI < 8)
            gemmA(Az, wf1z, hf, fctx + (size_t)(t + 1) * NB * NH, nullptr,
                  a_bm, a_bnI * 128, smem);
        else
            gemmA(Az, wh1, hh, nullptr, hb1, a_bm, (a_bnI - 8) * 128, smem);

        arrive_flag(&flagA[t * 8 + a_grp]);

        // ---------------- phase B ----------------
        wait_flag(&flagA[t * 8 + b_grp], 16);

        auto loadB = [&](int s, int c) {
            const int k0 = c << 6;
            uint32_t base = sbase + (uint32_t)(s * STG2) * 2u;
            #pragma unroll
            for (int i = 0; i < 2; i++) {
                int idx = tid + (i << 8);
                int m = idx >> 3, k8 = (idx & 7) << 3;
                cp16(base + (uint32_t)(AF + m * 72 + k8) * 2u, hf + (size_t)(b_bm + m) * NH + k0 + k8);
                cp16(base + (uint32_t)(AH + m * 72 + k8) * 2u, hh + (size_t)(b_bm + m) * NH + k0 + k8);
            }
            {
                int n = tid >> 3, k8 = (tid & 7) << 3;
                cp16(base + (uint32_t)(BF + n * 72 + k8) * 2u, wf2 + (size_t)(b_bn + n) * NH + k0 + k8);
                cp16(base + (uint32_t)(BH + n * 72 + k8) * 2u, wh2 + (size_t)(b_bn + n) * NH + k0 + k8);
            }
            asm volatile("cp.async.commit_group;" ::: "memory");
        };

        float ad[2][4], ap_[2][4];
        #pragma unroll
        for (int nt = 0; nt < 2; nt++)
            #pragma unroll
            for (int r = 0; r < 4; r++) { ad[nt][r] = 0.f; ap_[nt][r] = 0.f; }

        const int warpM = (wid & 3) * 16;
        const int warpNl = (wid >> 2) * 16;
        loadB(0, 0);
        loadB(1, 1);
        loadB(2, 2);
        for (int c = 0; c < 16; c++) {
            if (c <= 13)      asm volatile("cp.async.wait_group 2;" ::: "memory");
            else if (c == 14) asm volatile("cp.async.wait_group 1;" ::: "memory");
            else              asm volatile("cp.async.wait_group 0;" ::: "memory");
            __syncthreads();
            if (c + 3 < 16) loadB((c + 3) & 3, c + 3);

            const bf16* st = sm + (c & 3) * STG2;
            #pragma unroll
            for (int ks = 0; ks < 4; ks++) {
                const int kk = (ks << 4) + (lc << 1);
                const bf16* af = st + AF + (warpM + lr) * 72 + kk;
                uint32_t fa0 = *reinterpret_cast<const uint32_t*>(af);
                uint32_t fa1 = *reinterpret_cast<const uint32_t*>(af + 8 * 72);
                uint32_t fa2 = *reinterpret_cast<const uint32_t*>(af + 8);
                uint32_t fa3 = *reinterpret_cast<const uint32_t*>(af + 8 * 72 + 8);
                const bf16* ah = st + AH + (warpM + lr) * 72 + kk;
                uint32_t ha0 = *reinterpret_cast<const uint32_t*>(ah);
                uint32_t ha1 = *reinterpret_cast<const uint32_t*>(ah + 8 * 72);
                uint32_t ha2 = *reinterpret_cast<const uint32_t*>(ah + 8);
                uint32_t ha3 = *reinterpret_cast<const uint32_t*>(ah + 8 * 72 + 8);
                #pragma unroll
                for (int nt = 0; nt < 2; nt++) {
                    const bf16* bf_ = st + BF + (warpNl + nt * 8 + lr) * 72 + kk;
                    uint32_t b0 = *reinterpret_cast<const uint32_t*>(bf_);
                    uint32_t b1 = *reinterpret_cast<const uint32_t*>(bf_ + 8);
                    mma_bf16(ad[nt], fa0, fa1, fa2, fa3, b0, b1);
                    const bf16* bh_ = st + BH + (warpNl + nt * 8 + lr) * 72 + kk;
                    uint32_t c0 = *reinterpret_cast<const uint32_t*>(bh_);
                    uint32_t c1 = *reinterpret_cast<const uint32_t*>(bh_ + 8);
                    mma_bf16(ap_[nt], ha0, ha1, ha2, ha3, c0, c1);
                }
            }
        }

        // ---- fused step update ----
        const float dt = ts[t + 1] - ts[t];
        const float sq = sqrtf(dt);
        float* sred = (float*)smem;
        float pr_lo = 0.f, pr_hi = 0.f;

        #pragma unroll
        for (int nt = 0; nt < 2; nt++) {
            const int col = b_bn + warpNl + nt * 8 + (lc << 1);
            const float fb0 = fb2[col], fb1v = fb2[col + 1];
            const float hb0 = hb2[col], hb1v = hb2[col + 1];
            float d00 = ad[nt][0] + fb0, d01 = ad[nt][1] + fb1v;
            float d10 = ad[nt][2] + fb0, d11 = ad[nt][3] + fb1v;
            float p00 = ap_[nt][0] + hb0, p01 = ap_[nt][1] + hb1v;
            float p10 = ap_[nt][2] + hb0, p11 = ap_[nt][3] + hb1v;

            const float df0 = sqrtf(2.f / (BETAV * gamma[col]));
            const float df1 = sqrtf(2.f / (BETAV * gamma[col + 1]));
            float den0 = fabsf(df0) > EPSV ? df0 : ((df0 > 0.f) - (df0 < 0.f)) * EPSV;
            float den1 = fabsf(df1) > EPSV ? df1 : ((df1 > 0.f) - (df1 < 0.f)) * EPSV;
            float r00 = (d00 - p00) / den0, r01 = (d01 - p01) / den1;
            float r10 = (d10 - p10) / den0, r11 = (d11 - p11) / den1;
            pr_lo += r00 * r00 + r01 * r01;
            pr_hi += r10 * r10 + r11 * r11;

            const int b0r = b_bm + warpM + lr, b1r = b0r + 8;
            {
                size_t zi = (size_t)b0r * NL + col;
                float e0 = noise[((size_t)t * NB + b0r) * NL + col];
                float e1 = noise[((size_t)t * NB + b0r) * NL + col + 1];
                float zn0 = z[zi] + d00 * dt + df0 * sq * e0;
                float zn1 = z[zi + 1] + d01 * dt + df1 * sq * e1;
                z[zi] = zn0; z[zi + 1] = zn1;
                *reinterpret_cast<__nv_bfloat162*>(zs + ((size_t)b0r * NT + t + 1) * NL + col)
                    = __floats2bfloat162_rn(zn0, zn1);
            }
            {
                size_t zi = (size_t)b1r * NL + col;
                float e0 = noise[((size_t)t * NB + b1r) * NL + col];
                float e1 = noise[((size_t)t * NB + b1r) * NL + col + 1];
                float zn0 = z[zi] + d10 * dt + df0 * sq * e0;
                float zn1 = z[zi + 1] + d11 * dt + df1 * sq * e1;
                z[zi] = zn0; z[zi + 1] = zn1;
                *reinterpret_cast<__nv_bfloat162*>(zs + ((size_t)b1r * NT + t + 1) * NL + col)
                    = __floats2bfloat162_rn(zn0, zn1);
            }
        }

        pr_lo += __shfl_xor_sync(0xffffffff, pr_lo, 1);
        pr_lo += __shfl_xor_sync(0xffffffff, pr_lo, 2);
        pr_hi += __shfl_xor_sync(0xffffffff, pr_hi, 1);
        pr_hi += __shfl_xor_sync(0xffffffff, pr_hi, 2);
        const int ngrp = wid >> 2;
        __syncthreads();
        if (lc == 0) {
            sred[(warpM + lr) * 2 + ngrp] = pr_lo;
            sred[(warpM + lr + 8) * 2 + ngrp] = pr_hi;
        }
        __syncthreads();
        if (tid < 64)
            dkl8[b_ng * NB + b_bm + tid] += (sred[tid * 2] + sred[tid * 2 + 1]) * dt;

        arrive_flag(&flagB[t * 8 + b_grp]);
    }
}

// ---------------- finalize -----------------------------------------------------
__global__ void finalize_k(const float* __restrict__ partials, int np,
                           const float* __restrict__ dkl8, const float* __restrict__ kl0,
                           const float* __restrict__ nstd_p, float* __restrict__ out)
{
    __shared__ float sh[256];
    int tid = threadIdx.x;
    float s = 0.f;
    for (int i = tid; i < np; i += 256) s += partials[i];
    float tot = block_reduce_sum_256(s, sh);

    float s2 = 0.f;
    for (int i = tid; i < 8 * NB; i += 256) s2 += dkl8[i];
    float dkl_tot = block_reduce_sum_256(s2, sh);

    float s3 = 0.f;
    for (int i = tid; i < NB; i += 256) s3 += kl0[i];
    float kl0_tot = block_reduce_sum_256(s3, sh);

    if (tid == 0) {
        float nstd = nstd_p[0];
        float cst = (float)NT * (float)ND * (-logf(nstd) - 0.5f * LOG2PI);
        float log_pxs = tot / (float)NB + cst;
        out[0] = -log_pxs;
        out[1] = dkl_tot / (float)NB + kl0_tot / (float)NB;
    }
}

// ---------------- launch ------------------------------------------------------
#define SMEM128 (2 * (128*72 + 128*72) * 2)   // 73728

extern "C" void kernel_launch(void* const* d_in, const int* in_sizes, int n_in,
                              void* d_out, int out_size)
{
    const float* xs        = (const float*)d_in[0];
    const float* ts        = (const float*)d_in[1];
    const float* noise_std = (const float*)d_in[2];
    const float* eps0      = (const float*)d_in[3];
    const float* noise     = (const float*)d_in[4];
    const float* enc_w1    = (const float*)d_in[5];
    const float* enc_b1    = (const float*)d_in[6];
    const float* enc_w2    = (const float*)d_in[7];
    const float* enc_b2    = (const float*)d_in[8];
    const float* qz0_w     = (const float*)d_in[9];
    const float* qz0_b     = (const float*)d_in[10];
    const float* f_w1      = (const float*)d_in[11];
    const float* f_b1      = (const float*)d_in[12];
    const float* f_w2      = (const float*)d_in[13];
    const float* f_b2      = (const float*)d_in[14];
    const float* h_w1      = (const float*)d_in[15];
    const float* h_b1      = (const float*)d_in[16];
    const float* h_w2      = (const float*)d_in[17];
    const float* h_b2      = (const float*)d_in[18];
    const float* proj_w    = (const float*)d_in[19];
    const float* proj_b    = (const float*)d_in[20];
    const float* pz0_mean  = (const float*)d_in[21];
    const float* pz0_logstd= (const float*)d_in[22];
    const float* gamma     = (const float*)d_in[23];

    bf16 *y1, *ctx, *xst, *zs, *hf, *hh, *wtb, *fctx;
    float *z, *q, *dkl8, *kl0, *partials;
    unsigned *flagA, *flagB;
    cudaGetSymbolAddress((void**)&y1, g_y1);
    cudaGetSymbolAddress((void**)&ctx, g_ctx);
    cudaGetSymbolAddress((void**)&xst, g_xst);
    cudaGetSymbolAddress((void**)&zs, g_zs);
    cudaGetSymbolAddress((void**)&z, g_z);
    cudaGetSymbolAddress((void**)&hf, g_hf);
    cudaGetSymbolAddress((void**)&hh, g_hh);
    cudaGetSymbolAddress((void**)&q, g_q);
    cudaGetSymbolAddress((void**)&fctx, g_fctx);
    cudaGetSymbolAddress((void**)&wtb, g_wtb);
    cudaGetSymbolAddress((void**)&dkl8, g_dkl8);
    cudaGetSymbolAddress((void**)&kl0, g_kl0);
    cudaGetSymbolAddress((void**)&partials, g_partials);
    cudaGetSymbolAddress((void**)&flagA, g_flagA);
    cudaGetSymbolAddress((void**)&flagB, g_flagB);

    cudaFuncSetAttribute(gemm_bf<128,1,1,0,0>, cudaFuncAttributeMaxDynamicSharedMemorySize, SMEM128);
    cudaFuncSetAttribute(gemm_bf<128,0,1,0,0>, cudaFuncAttributeMaxDynamicSharedMemorySize, SMEM128);
    cudaFuncSetAttribute(gemm_bf<128,0,0,0,0>, cudaFuncAttributeMaxDynamicSharedMemorySize, SMEM128);
    cudaFuncSetAttribute(gemm_bf<128,0,0,1,0>, cudaFuncAttributeMaxDynamicSharedMemorySize, SMEM128);
    cudaFuncSetAttribute(gemm_bf<128,0,0,0,1>, cudaFuncAttributeMaxDynamicSharedMemorySize, SMEM128);
    cudaFuncSetAttribute(scan_k, cudaFuncAttributeMaxDynamicSharedMemorySize, SMEMP);

    const int M = NB * NT;

    // ---- launch 1: fused prep (transposes + xs copy + flag/dkl reset) ----
    {
        PrepArgs pa{};
        const float* srcs[9] = {enc_w1, enc_w2, qz0_w, f_w1, f_w1 + 256 * NH,
                                f_w2, h_w1, h_w2, proj_w};
        int offs[9] = {W_ENC1, W_ENC2, W_QZ0, W_F1Z, W_F1C, W_F2, W_H1, W_H2, W_PROJ};
        int Ks[9]   = {256, 1024, 512, 256, 512, 1024, 256, 1024, 256};
        int Ns[9]   = {1024, 256, 512, 1024, 1024, 256, 1024, 256, 256};
        int off = 0;
        for (int i = 0; i < 9; i++) {
            pa.src[i] = srcs[i]; pa.off[i] = offs[i]; pa.K[i] = Ks[i]; pa.N[i] = Ns[i];
            pa.tileOff[i] = off;
            off += (Ns[i] >> 5) * (Ks[i] >> 5);
        }
        pa.tileOff[9] = off;           // 2368
        pa.xs = xs;
        const int nCopy = (int)((size_t)M * ND / 1024);   // 16384
        prep_k<<<off + nCopy, 256>>>(pa, wtb, ctx, xst, dkl8, flagA, flagB);
    }

    GArgs zg{};

    // ---- launches 2-3: encoder ----
    {
        GArgs a{xst, ND, wtb + W_ENC1, enc_b1, y1, NH, ND};
        gemm_bf<128,1,1,0,0><<<dim3(NH/128, M/128), 256, SMEM128>>>(a, a, M/128, nullptr, nullptr, nullptr);
    }
    {
        GArgs a{y1, NH, wtb + W_ENC2, enc_b2, ctx, 512, NH};
        gemm_bf<128,0,1,0,0><<<dim3(NL/128, M/128), 256, SMEM128>>>(a, a, M/128, nullptr, nullptr, nullptr);
    }

    // ---- launch 4: fctx ----
    {
        GArgs a{ctx, 512, wtb + W_F1C, f_b1, fctx, NH, 512};
        gemm_bf<128,0,0,0,1><<<dim3(NH/128, M/128), 256, SMEM128>>>(a, a, M/128, nullptr, nullptr, nullptr);
    }

    // ---- launch 5: q ----
    {
        GArgs a{ctx, NT * 512, wtb + W_QZ0, qz0_b, q, 512, 512};
        gemm_bf<128,0,0,0,0><<<dim3(512/128, NB/128), 256, SMEM128>>>(a, a, NB/128, nullptr, nullptr, nullptr);
    }

    // ---- launch 6: persistent scan (z0 + diffv fused; ncu -s 5 captures this) ----
    scan_k<<<128, 256, SMEMP>>>(ts, noise, z, zs, hf, hh,
                                wtb + W_F1Z, wtb + W_H1, wtb + W_F2, wtb + W_H2,
                                h_b1, f_b2, h_b2, fctx, gamma, dkl8, flagA, flagB,
                                q, eps0, pz0_mean, pz0_logstd, kl0);

    // ---- launch 7: decoder fused with NLL reduction ----
    {
        GArgs a{zs, NL, wtb + W_PROJ, proj_b, nullptr, ND, NL};
        gemm_bf<128,0,0,1,0><<<dim3(ND/128, M/128), 256, SMEM128>>>(a, zg, M/128, xs, noise_std, partials);
    }

    // ---- launch 8: finalize ----
    finalize_k<<<1, 256>>>(partials, (M/128) * (ND/128), dkl8, kl0, noise_std, (float*)d_out);

    (void)in_sizes; (void)n_in; (void)out_size;
}

// round 14
// speedup vs baseline: 1.0717x; 1.0559x over previous
#include <cuda_runtime.h>
#include <cuda_bf16.h>
#include <math.h>
#include <stdint.h>

// ---------------- problem dims ------------------------------------------------
#define NB 1024
#define NT 64
#define ND 256
#define NL 256
#define NH 1024
#define EPSV 1e-7f
#define LOG2PI 1.8378770664093453f
#define BETAV (1.0f/3.0f)

typedef __nv_bfloat16 bf16;

// ---------------- scratch (device globals) ------------------------------------
__device__ __align__(16) bf16  g_y1[(size_t)NB * NT * NH];
__device__ __align__(16) bf16  g_ctx[(size_t)NB * NT * 512];
__device__ __align__(16) bf16  g_xst[(size_t)NB * NT * ND];
__device__ __align__(16) bf16  g_zs[(size_t)NB * NT * NL];
__device__ __align__(16) float g_z[NB * NL];
__device__ __align__(16) bf16  g_hf[NB * NH];
__device__ __align__(16) bf16  g_hh[NB * NH];
__device__ __align__(16) float g_q[NB * 512];
__device__ __align__(16) bf16  g_fctx[(size_t)NT * NB * NH];   // [t][b][1024] bf16
__device__ __align__(16) bf16  g_wtb[2424832];
__device__ float g_dkl8[8 * NB];
__device__ float g_kl0[NB];
__device__ float g_partials[4096];
__device__ unsigned g_flagA[NT * 8];   // phase-A done counters per (t, row-group)
__device__ unsigned g_flagB[NT * 8];   // phase-B done (t<63); slots 504..511 = z0-done

// weight offsets in g_wtb (elements), stored transposed [N][K]
#define W_ENC1 0
#define W_ENC2 262144
#define W_QZ0  524288
#define W_F1Z  786432
#define W_F1C  1048576
#define W_F2   1572864
#define W_H1   1835008
#define W_H2   2097152
#define W_PROJ 2359296

// ---------------- helpers -----------------------------------------------------
__device__ __forceinline__ uint32_t s2u(const void* p) {
    uint32_t a;
    asm("{ .reg .u64 t; cvta.to.shared.u64 t, %1; cvt.u32.u64 %0, t; }" : "=r"(a) : "l"(p));
    return a;
}
__device__ __forceinline__ void cp16(uint32_t saddr, const void* g) {
    asm volatile("cp.async.cg.shared.global [%0], [%1], 16;" :: "r"(saddr), "l"(g));
}
__device__ __forceinline__ void mma_bf16(float* c, uint32_t a0, uint32_t a1, uint32_t a2, uint32_t a3,
                                         uint32_t b0, uint32_t b1) {
    asm volatile("mma.sync.aligned.m16n8k16.row.col.f32.bf16.bf16.f32 "
                 "{%0,%1,%2,%3},{%4,%5,%6,%7},{%8,%9},{%0,%1,%2,%3};"
                 : "+f"(c[0]), "+f"(c[1]), "+f"(c[2]), "+f"(c[3])
                 : "r"(a0), "r"(a1), "r"(a2), "r"(a3), "r"(b0), "r"(b1));
}
__device__ __forceinline__ float block_reduce_sum_256(float v, float* sh) {
    int tid = threadIdx.x;
    sh[tid] = v;
    __syncthreads();
    #pragma unroll
    for (int s = 128; s > 0; s >>= 1) {
        if (tid < s) sh[tid] += sh[tid + s];
        __syncthreads();
    }
    float r = sh[0];
    __syncthreads();
    return r;
}
__device__ __forceinline__ void wait_flag(unsigned* f, unsigned tgt) {
    if (threadIdx.x == 0) {
        unsigned v;
        do {
            asm volatile("ld.acquire.gpu.u32 %0, [%1];" : "=r"(v) : "l"(f) : "memory");
        } while (v < tgt);
    }
    __syncthreads();
}
__device__ __forceinline__ void arrive_flag(unsigned* f) {
    __syncthreads();
    if (threadIdx.x == 0)
        asm volatile("red.release.gpu.add.u32 [%0], 1;" :: "l"(f) : "memory");
}

// ---------------- standalone bf16 GEMM ----------------------------------------
struct GArgs {
    const bf16* A; int lda;
    const bf16* W;
    const float* bias;
    void* C; int ldc;
    int K;
};

// __launch_bounds__(256, 2): cap regs at 128 so 2 CTAs co-reside per SM
// (R13 profile: 134 regs -> 1 CTA/SM, occ 12.4%, tensor 38%).
template<int BMT, int ACT, int OUTBF, int EPI, int TSCAT>
__global__ void __launch_bounds__(256, 2)
gemm_bf(GArgs g0, GArgs g1, int mSplit,
        const float* __restrict__ xs, const float* __restrict__ nstd_p,
        float* __restrict__ partials)
{
    extern __shared__ char smem[];
    constexpr int MT  = (BMT + 31) / 32;
    constexpr int ASZ = BMT * 72;
    constexpr int BSZ = 128 * 72;
    constexpr int STG = ASZ + BSZ;

    const int tid  = threadIdx.x;
    const int wid  = tid >> 5;
    const int lane = tid & 31;
    const int lr   = lane >> 2;
    const int lc   = lane & 3;

    const bool grp1 = ((int)blockIdx.y >= mSplit);
    const GArgs g = grp1 ? g1 : g0;
    const int bm = (grp1 ? ((int)blockIdx.y - mSplit) : (int)blockIdx.y) * BMT;
    const int bn = (int)blockIdx.x * 128;

    bf16* sm = (bf16*)smem;
    const uint32_t sbase = s2u(smem);
    const int warpM = (wid >> 2) * (BMT / 2);
    const int warpN = (wid & 3) * 32;

    auto loadtile = [&](int s, int c) {
        const int k0 = c << 6;
        uint32_t sA = sbase + (uint32_t)(s * STG) * 2u;
        uint32_t sB = sA + (uint32_t)ASZ * 2u;
        const bf16* Ag = g.A + (size_t)bm * g.lda + k0;
        #pragma unroll
        for (int i = 0; i < BMT / 32; i++) {
            int idx = tid + (i << 8);
            int m = idx >> 3, k8 = (idx & 7) << 3;
            cp16(sA + (uint32_t)(m * 72 + k8) * 2u, Ag + (size_t)m * g.lda + k8);
        }
        const bf16* Wg = g.W + (size_t)bn * g.K + k0;
        #pragma unroll
        for (int i = 0; i < 4; i++) {
            int idx = tid + (i << 8);
            int n = idx >> 3, k8 = (idx & 7) << 3;
            cp16(sB + (uint32_t)(n * 72 + k8) * 2u, Wg + (size_t)n * g.K + k8);
        }
        asm volatile("cp.async.commit_group;" ::: "memory");
    };

    float acc[MT][4][4];
    #pragma unroll
    for (int mt = 0; mt < MT; mt++)
        #pragma unroll
        for (int nt = 0; nt < 4; nt++)
            #pragma unroll
            for (int r = 0; r < 4; r++) acc[mt][nt][r] = 0.f;

    const int nch = g.K >> 6;
    loadtile(0, 0);
    if (nch > 1) loadtile(1, 1);

    for (int c = 0; c < nch; c++) {
        if (c + 1 < nch) asm volatile("cp.async.wait_group 1;" ::: "memory");
        else             asm volatile("cp.async.wait_group 0;" ::: "memory");
        __syncthreads();
        const bf16* As = sm + (c & 1) * STG;
        const bf16* Bs = As + ASZ;
        #pragma unroll
        for (int ks = 0; ks < 4; ks++) {
            const int kk = (ks << 4) + (lc << 1);
            uint32_t b[4][2];
            #pragma unroll
            for (int nt = 0; nt < 4; nt++) {
                const bf16* bp = Bs + (warpN + nt * 8 + lr) * 72 + kk;
                b[nt][0] = *reinterpret_cast<const uint32_t*>(bp);
                b[nt][1] = *reinterpret_cast<const uint32_t*>(bp + 8);
            }
            #pragma unroll
            for (int mt = 0; mt < MT; mt++) {
                const bf16* ap = As + (warpM + mt * 16 + lr) * 72 + kk;
                uint32_t a0 = *reinterpret_cast<const uint32_t*>(ap);
                uint32_t a1 = *reinterpret_cast<const uint32_t*>(ap + 8 * 72);
                uint32_t a2 = *reinterpret_cast<const uint32_t*>(ap + 8);
                uint32_t a3 = *reinterpret_cast<const uint32_t*>(ap + 8 * 72 + 8);
                #pragma unroll
                for (int nt = 0; nt < 4; nt++)
                    mma_bf16(acc[mt][nt], a0, a1, a2, a3, b[nt][0], b[nt][1]);
            }
        }
        __syncthreads();
        if (c + 2 < nch) loadtile(c & 1, c + 2);
    }

    float loc = 0.f;
    const float invs = EPI ? (1.f / nstd_p[0]) : 0.f;
    #pragma unroll
    for (int mt = 0; mt < MT; mt++) {
        const int row0 = bm + warpM + mt * 16 + lr;
        #pragma unroll
        for (int nt = 0; nt < 4; nt++) {
            const int col = bn + warpN + nt * 8 + (lc << 1);
            float2 bb = *reinterpret_cast<const float2*>(g.bias + col);
            float v00 = acc[mt][nt][0] + bb.x;
            float v01 = acc[mt][nt][1] + bb.y;
            float v10 = acc[mt][nt][2] + bb.x;
            float v11 = acc[mt][nt][3] + bb.y;
            if (ACT) { v00 = tanhf(v00); v01 = tanhf(v01); v10 = tanhf(v10); v11 = tanhf(v11); }
            if (EPI) {
                float2 x0 = *reinterpret_cast<const float2*>(xs + (size_t)row0 * g.ldc + col);
                float2 x1 = *reinterpret_cast<const float2*>(xs + (size_t)(row0 + 8) * g.ldc + col);
                float r0 = (x0.x - v00) * invs, r1 = (x0.y - v01) * invs;
                float r2 = (x1.x - v10) * invs, r3 = (x1.y - v11) * invs;
                loc += r0 * r0 + r1 * r1 + r2 * r2 + r3 * r3;
            } else if (TSCAT) {
                bf16* Cb = (bf16*)g.C;
                size_t o0 = ((size_t)(row0 & 63) * NB + (row0 >> 6)) * NH + col;
                int row1 = row0 + 8;
                size_t o1 = ((size_t)(row1 & 63) * NB + (row1 >> 6)) * NH + col;
                *reinterpret_cast<__nv_bfloat162*>(Cb + o0) = __floats2bfloat162_rn(v00, v01);
                *reinterpret_cast<__nv_bfloat162*>(Cb + o1) = __floats2bfloat162_rn(v10, v11);
            } else if (OUTBF) {
                bf16* Cb = (bf16*)g.C;
                *reinterpret_cast<__nv_bfloat162*>(Cb + (size_t)row0 * g.ldc + col) = __floats2bfloat162_rn(v00, v01);
                *reinterpret_cast<__nv_bfloat162*>(Cb + (size_t)(row0 + 8) * g.ldc + col) = __floats2bfloat162_rn(v10, v11);
            } else {
                float* Cf = (float*)g.C;
                *reinterpret_cast<float2*>(Cf + (size_t)row0 * g.ldc + col) = make_float2(v00, v01);
                *reinterpret_cast<float2*>(Cf + (size_t)(row0 + 8) * g.ldc + col) = make_float2(v10, v11);
            }
        }
    }
    if (EPI) {
        __syncthreads();
        float tot = block_reduce_sum_256(loc, (float*)smem);
        if (tid == 0) partials[blockIdx.y * gridDim.x + blockIdx.x] = -0.5f * tot;
    }
}

// ---------------- fused prologue: transposes + xs copy + resets ----------------
struct PrepArgs {
    const float* src[9];
    int off[9];
    int K[9], N[9];
    int tileOff[10];
    const float* xs;
};

__global__ void __launch_bounds__(256)
prep_k(PrepArgs pa, bf16* __restrict__ wtb, bf16* __restrict__ ctx, bf16* __restrict__ xst,
       float* __restrict__ dkl8, unsigned* __restrict__ flagA, unsigned* __restrict__ flagB)
{
    __shared__ float t[32][33];
    const int bx = blockIdx.x;
    const int tid = threadIdx.x;

    if (bx == 0) {
        #pragma unroll
        for (int i = 0; i < 32; i++) dkl8[tid + i * 256] = 0.f;
        #pragma unroll
        for (int i = 0; i < 2; i++) {
            flagA[tid + i * 256] = 0u;
            flagB[tid + i * 256] = 0u;
        }
    }

    if (bx < pa.tileOff[9]) {
        int m = 0;
        #pragma unroll
        for (int i = 1; i < 9; i++) if (bx >= pa.tileOff[i]) m = i;
        const int local = bx - pa.tileOff[m];
        const int K = pa.K[m], N = pa.N[m];
        const int nTiles = N >> 5;
        const int n0 = (local % nTiles) << 5;
        const int k0 = (local / nTiles) << 5;
        const float* W = pa.src[m];
        bf16* Wt = wtb + pa.off[m];
        const int tx = tid & 31, ty = tid >> 5;
        #pragma unroll
        for (int j = 0; j < 4; j++)
            t[ty + j * 8][tx] = W[(size_t)(k0 + ty + j * 8) * N + n0 + tx];
        __syncthreads();
        #pragma unroll
        for (int j = 0; j < 4; j++)
            Wt[(size_t)(n0 + ty + j * 8) * K + k0 + tx] = __float2bfloat16(t[tx][ty + j * 8]);
    } else {
        size_t i0 = ((size_t)(bx - pa.tileOff[9]) << 10) + ((size_t)tid << 2);
        float4 v = *reinterpret_cast<const float4*>(pa.xs + i0);
        float vv[4] = {v.x, v.y, v.z, v.w};
        #pragma unroll
        for (int u = 0; u < 4; u++) {
            size_t idx = i0 + u;
            size_t bt = idx >> 8, d = idx & 255;
            bf16 b = __float2bfloat16(vv[u]);
            ctx[bt * 512 + 256 + d] = b;
            xst[idx] = b;
        }
    }
}

// ---------------- persistent scan ---------------------------------------------
__device__ void gemmA(const bf16* A, const bf16* W, bf16* C,
                      const bf16* fadd, const float* bias,
                      int bm, int bn, char* smem)
{
    constexpr int lda = NT * NL;
    constexpr int ASZ = 128 * 72, STG = 2 * 128 * 72;
    const int tid = threadIdx.x;
    const int wid = tid >> 5, lane = tid & 31;
    const int lr = lane >> 2, lc = lane & 3;
    bf16* sm = (bf16*)smem;
    const uint32_t sbase = s2u(smem);
    const int warpM = (wid >> 2) * 64;
    const int warpN = (wid & 3) * 32;

    auto loadtile = [&](int s, int c) {
        const int k0 = c << 6;
        uint32_t sA = sbase + (uint32_t)(s * STG) * 2u;
        uint32_t sB = sA + (uint32_t)ASZ * 2u;
        #pragma unroll
        for (int i = 0; i < 4; i++) {
            int idx = tid + (i << 8);
            int m = idx >> 3, k8 = (idx & 7) << 3;
            cp16(sA + (uint32_t)(m * 72 + k8) * 2u, A + (size_t)(bm + m) * lda + k0 + k8);
        }
        #pragma unroll
        for (int i = 0; i < 4; i++) {
            int idx = tid + (i << 8);
            int n = idx >> 3, k8 = (idx & 7) << 3;
            cp16(sB + (uint32_t)(n * 72 + k8) * 2u, W + (size_t)(bn + n) * 256 + k0 + k8);
        }
        asm volatile("cp.async.commit_group;" ::: "memory");
    };

    float acc[4][4][4];
    #pragma unroll
    for (int mt = 0; mt < 4; mt++)
        #pragma unroll
        for (int nt = 0; nt < 4; nt++)
            #pragma unroll
            for (int r = 0; r < 4; r++) acc[mt][nt][r] = 0.f;

    loadtile(0, 0);
    loadtile(1, 1);
    loadtile(2, 2);
    for (int c = 0; c < 4; c++) {
        if (c <= 1)      asm volatile("cp.async.wait_group 2;" ::: "memory");
        else if (c == 2) asm volatile("cp.async.wait_group 1;" ::: "memory");
        else             asm volatile("cp.async.wait_group 0;" ::: "memory");
        __syncthreads();
        if (c + 3 < 4) loadtile(c + 3, c + 3);

        const bf16* As = sm + c * STG;
        const bf16* Bs = As + ASZ;
        #pragma unroll
        for (int ks = 0; ks < 4; ks++) {
            const int kk = (ks << 4) + (lc << 1);
            uint32_t b[4][2];
            #pragma unroll
            for (int nt = 0; nt < 4; nt++) {
                const bf16* bp = Bs + (warpN + nt * 8 + lr) * 72 + kk;
                b[nt][0] = *reinterpret_cast<const uint32_t*>(bp);
                b[nt][1] = *reinterpret_cast<const uint32_t*>(bp + 8);
            }
            #pragma unroll
            for (int mt = 0; mt < 4; mt++) {
                const bf16* ap = As + (warpM + mt * 16 + lr) * 72 + kk;
                uint32_t a0 = *reinterpret_cast<const uint32_t*>(ap);
                uint32_t a1 = *reinterpret_cast<const uint32_t*>(ap + 8 * 72);
                uint32_t a2 = *reinterpret_cast<const uint32_t*>(ap + 8);
                uint32_t a3 = *reinterpret_cast<const uint32_t*>(ap + 8 * 72 + 8);
                #pragma unroll
                for (int nt = 0; nt < 4; nt++)
                    mma_bf16(acc[mt][nt], a0, a1, a2, a3, b[nt][0], b[nt][1]);
            }
        }
    }

    #pragma unroll
    for (int mt = 0; mt < 4; mt++) {
        const int row0 = bm + warpM + mt * 16 + lr;
        #pragma unroll
        for (int nt = 0; nt < 4; nt++) {
            const int gcol = bn + warpN + nt * 8 + (lc << 1);
            float a00, a01, a10, a11;
            if (fadd) {
                __nv_bfloat162 f0 = *reinterpret_cast<const __nv_bfloat162*>(fadd + (size_t)row0 * NH + gcol);
                __nv_bfloat162 f1 = *reinterpret_cast<const __nv_bfloat162*>(fadd + (size_t)(row0 + 8) * NH + gcol);
                a00 = __low2float(f0); a01 = __high2float(f0);
                a10 = __low2float(f1); a11 = __high2float(f1);
            } else {
                float2 bb = *reinterpret_cast<const float2*>(bias + gcol);
                a00 = bb.x; a01 = bb.y; a10 = bb.x; a11 = bb.y;
            }
            float v00 = tanhf(acc[mt][nt][0] + a00);
            float v01 = tanhf(acc[mt][nt][1] + a01);
            float v10 = tanhf(acc[mt][nt][2] + a10);
            float v11 = tanhf(acc[mt][nt][3] + a11);
            *reinterpret_cast<__nv_bfloat162*>(C + (size_t)row0 * NH + gcol) = __floats2bfloat162_rn(v00, v01);
            *reinterpret_cast<__nv_bfloat162*>(C + (size_t)(row0 + 8) * NH + gcol) = __floats2bfloat162_rn(v10, v11);
        }
    }
}

#define SMEMP 147456

__global__ void __launch_bounds__(256)
scan_k(const float* __restrict__ ts, const float* __restrict__ noise,
       float* __restrict__ z, bf16* __restrict__ zs,
       bf16* __restrict__ hf, bf16* __restrict__ hh,
       const bf16* __restrict__ wf1z, const bf16* __restrict__ wh1,
       const bf16* __restrict__ wf2, const bf16* __restrict__ wh2,
       const float* __restrict__ hb1,
       const float* __restrict__ fb2, const float* __restrict__ hb2,
       const bf16* __restrict__ fctx,
       const float* __restrict__ gamma, float* __restrict__ dkl8,
       unsigned* flagA, unsigned* flagB,
       const float* __restrict__ q, const float* __restrict__ eps0,
       const float* __restrict__ pm, const float* __restrict__ pl,
       float* __restrict__ kl0)
{
    extern __shared__ char smem[];
    const int tid = threadIdx.x;
    const int cta = blockIdx.x;
    const int wid = tid >> 5, lane = tid & 31;
    const int lr = lane >> 2, lc = lane & 3;

    // ---- fused z0 prologue ----
    {
        const int b = cta * 8 + wid;
        float part = 0.f;
        #pragma unroll
        for (int j = 0; j < 8; j++) {
            const int l = lane + j * 32;
            float qm = q[b * 512 + l];
            float ql = q[b * 512 + 256 + l];
            float z0 = qm + expf(ql) * eps0[b * NL + l];
            z[b * NL + l] = z0;
            zs[(size_t)b * NT * NL + l] = __float2bfloat16(z0);
            float pmv = pm[l], plv = pl[l];
            float dm = qm - pmv;
            part += plv - ql + (expf(2.f * ql) + dm * dm) / (2.f * expf(2.f * plv)) - 0.5f;
        }
        #pragma unroll
        for (int s = 16; s > 0; s >>= 1) part += __shfl_xor_sync(0xffffffff, part, s);
        if (lane == 0) kl0[b] = part;
    }
    arrive_flag(&flagB[504 + (cta >> 4)]);

    const int a_bm = (cta >> 4) * 128;
    const int a_bnI = cta & 15;
    const int a_grp = a_bm >> 7;

    const int b_bm = (cta >> 3) * 64;
    const int b_ng = cta & 7;
    const int b_bn = b_ng * 32;
    const int b_grp = b_bm >> 7;

    constexpr int AF = 0, AH = 64 * 72, BF = 128 * 72, BH = 128 * 72 + 32 * 72;
    constexpr int STG2 = 192 * 72;
    bf16* sm = (bf16*)smem;
    const uint32_t sbase = s2u(smem);

    for (int t = 0; t < NT - 1; t++) {
        // ---------------- phase A ----------------
        wait_flag(&flagB[(t == 0) ? (504 + a_grp) : ((t - 1) * 8 + a_grp)], 16);

        const bf16* Az = zs + (size_t)t * NL;
        if (a_bnI < 8)
            gemmA(Az, wf1z, hf, fctx + (size_t)(t + 1) * NB * NH, nullptr,
                  a_bm, a_bnI * 128, smem);
        else
            gemmA(Az, wh1, hh, nullptr, hb1, a_bm, (a_bnI - 8) * 128, smem);

        arrive_flag(&flagA[t * 8 + a_grp]);

        // ---------------- phase B ----------------
        wait_flag(&flagA[t * 8 + b_grp], 16);

        auto loadB = [&](int s, int c) {
            const int k0 = c << 6;
            uint32_t base = sbase + (uint32_t)(s * STG2) * 2u;
            #pragma unroll
            for (int i = 0; i < 2; i++) {
                int idx = tid + (i << 8);
                int m = idx >> 3, k8 = (idx & 7) << 3;
                cp16(base + (uint32_t)(AF + m * 72 + k8) * 2u, hf + (size_t)(b_bm + m) * NH + k0 + k8);
                cp16(base + (uint32_t)(AH + m * 72 + k8) * 2u, hh + (size_t)(b_bm + m) * NH + k0 + k8);
            }
            {
                int n = tid >> 3, k8 = (tid & 7) << 3;
                cp16(base + (uint32_t)(BF + n * 72 + k8) * 2u, wf2 + (size_t)(b_bn + n) * NH + k0 + k8);
                cp16(base + (uint32_t)(BH + n * 72 + k8) * 2u, wh2 + (size_t)(b_bn + n) * NH + k0 + k8);
            }
            asm volatile("cp.async.commit_group;" ::: "memory");
        };

        float ad[2][4], ap_[2][4];
        #pragma unroll
        for (int nt = 0; nt < 2; nt++)
            #pragma unroll
            for (int r = 0; r < 4; r++) { ad[nt][r] = 0.f; ap_[nt][r] = 0.f; }

        const int warpM = (wid & 3) * 16;
        const int warpNl = (wid >> 2) * 16;
        loadB(0, 0);
        loadB(1, 1);
        loadB(2, 2);
        for (int c = 0; c < 16; c++) {
            if (c <= 13)      asm volatile("cp.async.wait_group 2;" ::: "memory");
            else if (c == 14) asm volatile("cp.async.wait_group 1;" ::: "memory");
            else              asm volatile("cp.async.wait_group 0;" ::: "memory");
            __syncthreads();
            if (c + 3 < 16) loadB((c + 3) & 3, c + 3);

            const bf16* st = sm + (c & 3) * STG2;
            #pragma unroll
            for (int ks = 0; ks < 4; ks++) {
                const int kk = (ks << 4) + (lc << 1);
                const bf16* af = st + AF + (warpM + lr) * 72 + kk;
                uint32_t fa0 = *reinterpret_cast<const uint32_t*>(af);
                uint32_t fa1 = *reinterpret_cast<const uint32_t*>(af + 8 * 72);
                uint32_t fa2 = *reinterpret_cast<const uint32_t*>(af + 8);
                uint32_t fa3 = *reinterpret_cast<const uint32_t*>(af + 8 * 72 + 8);
                const bf16* ah = st + AH + (warpM + lr) * 72 + kk;
                uint32_t ha0 = *reinterpret_cast<const uint32_t*>(ah);
                uint32_t ha1 = *reinterpret_cast<const uint32_t*>(ah + 8 * 72);
                uint32_t ha2 = *reinterpret_cast<const uint32_t*>(ah + 8);
                uint32_t ha3 = *reinterpret_cast<const uint32_t*>(ah + 8 * 72 + 8);
                #pragma unroll
                for (int nt = 0; nt < 2; nt++) {
                    const bf16* bf_ = st + BF + (warpNl + nt * 8 + lr) * 72 + kk;
                    uint32_t b0 = *reinterpret_cast<const uint32_t*>(bf_);
                    uint32_t b1 = *reinterpret_cast<const uint32_t*>(bf_ + 8);
                    mma_bf16(ad[nt], fa0, fa1, fa2, fa3, b0, b1);
                    const bf16* bh_ = st + BH + (warpNl + nt * 8 + lr) * 72 + kk;
                    uint32_t c0 = *reinterpret_cast<const uint32_t*>(bh_);
                    uint32_t c1 = *reinterpret_cast<const uint32_t*>(bh_ + 8);
                    mma_bf16(ap_[nt], ha0, ha1, ha2, ha3, c0, c1);
                }
            }
        }

        // ---- fused step update ----
        const float dt = ts[t + 1] - ts[t];
        const float sq = sqrtf(dt);
        float* sred = (float*)smem;
        float pr_lo = 0.f, pr_hi = 0.f;

        #pragma unroll
        for (int nt = 0; nt < 2; nt++) {
            const int col = b_bn + warpNl + nt * 8 + (lc << 1);
            const float fb0 = fb2[col], fb1v = fb2[col + 1];
            const float hb0 = hb2[col], hb1v = hb2[col + 1];
            float d00 = ad[nt][0] + fb0, d01 = ad[nt][1] + fb1v;
            float d10 = ad[nt][2] + fb0, d11 = ad[nt][3] + fb1v;
            float p00 = ap_[nt][0] + hb0, p01 = ap_[nt][1] + hb1v;
            float p10 = ap_[nt][2] + hb0, p11 = ap_[nt][3] + hb1v;

            const float df0 = sqrtf(2.f / (BETAV * gamma[col]));
            const float df1 = sqrtf(2.f / (BETAV * gamma[col + 1]));
            float den0 = fabsf(df0) > EPSV ? df0 : ((df0 > 0.f) - (df0 < 0.f)) * EPSV;
            float den1 = fabsf(df1) > EPSV ? df1 : ((df1 > 0.f) - (df1 < 0.f)) * EPSV;
            float r00 = (d00 - p00) / den0, r01 = (d01 - p01) / den1;
            float r10 = (d10 - p10) / den0, r11 = (d11 - p11) / den1;
            pr_lo += r00 * r00 + r01 * r01;
            pr_hi += r10 * r10 + r11 * r11;

            const int b0r = b_bm + warpM + lr, b1r = b0r + 8;
            {
                size_t zi = (size_t)b0r * NL + col;
                float e0 = noise[((size_t)t * NB + b0r) * NL + col];
                float e1 = noise[((size_t)t * NB + b0r) * NL + col + 1];
                float zn0 = z[zi] + d00 * dt + df0 * sq * e0;
                float zn1 = z[zi + 1] + d01 * dt + df1 * sq * e1;
                z[zi] = zn0; z[zi + 1] = zn1;
                *reinterpret_cast<__nv_bfloat162*>(zs + ((size_t)b0r * NT + t + 1) * NL + col)
                    = __floats2bfloat162_rn(zn0, zn1);
            }
            {
                size_t zi = (size_t)b1r * NL + col;
                float e0 = noise[((size_t)t * NB + b1r) * NL + col];
                float e1 = noise[((size_t)t * NB + b1r) * NL + col + 1];
                float zn0 = z[zi] + d10 * dt + df0 * sq * e0;
                float zn1 = z[zi + 1] + d11 * dt + df1 * sq * e1;
                z[zi] = zn0; z[zi + 1] = zn1;
                *reinterpret_cast<__nv_bfloat162*>(zs + ((size_t)b1r * NT + t + 1) * NL + col)
                    = __floats2bfloat162_rn(zn0, zn1);
            }
        }

        pr_lo += __shfl_xor_sync(0xffffffff, pr_lo, 1);
        pr_lo += __shfl_xor_sync(0xffffffff, pr_lo, 2);
        pr_hi += __shfl_xor_sync(0xffffffff, pr_hi, 1);
        pr_hi += __shfl_xor_sync(0xffffffff, pr_hi, 2);
        const int ngrp = wid >> 2;
        __syncthreads();
        if (lc == 0) {
            sred[(warpM + lr) * 2 + ngrp] = pr_lo;
            sred[(warpM + lr + 8) * 2 + ngrp] = pr_hi;
        }
        __syncthreads();
        if (tid < 64)
            dkl8[b_ng * NB + b_bm + tid] += (sred[tid * 2] + sred[tid * 2 + 1]) * dt;

        arrive_flag(&flagB[t * 8 + b_grp]);
    }
}

// ---------------- finalize -----------------------------------------------------
__global__ void finalize_k(const float* __restrict__ partials, int np,
                           const float* __restrict__ dkl8, const float* __restrict__ kl0,
                           const float* __restrict__ nstd_p, float* __restrict__ out)
{
    __shared__ float sh[256];
    int tid = threadIdx.x;
    float s = 0.f;
    for (int i = tid; i < np; i += 256) s += partials[i];
    float tot = block_reduce_sum_256(s, sh);

    float s2 = 0.f;
    for (int i = tid; i < 8 * NB; i += 256) s2 += dkl8[i];
    float dkl_tot = block_reduce_sum_256(s2, sh);

    float s3 = 0.f;
    for (int i = tid; i < NB; i += 256) s3 += kl0[i];
    float kl0_tot = block_reduce_sum_256(s3, sh);

    if (tid == 0) {
        float nstd = nstd_p[0];
        float cst = (float)NT * (float)ND * (-logf(nstd) - 0.5f * LOG2PI);
        float log_pxs = tot / (float)NB + cst;
        out[0] = -log_pxs;
        out[1] = dkl_tot / (float)NB + kl0_tot / (float)NB;
    }
}

// ---------------- launch ------------------------------------------------------
#define SMEM128 (2 * (128*72 + 128*72) * 2)   // 73728

extern "C" void kernel_launch(void* const* d_in, const int* in_sizes, int n_in,
                              void* d_out, int out_size)
{
    const float* xs        = (const float*)d_in[0];
    const float* ts        = (const float*)d_in[1];
    const float* noise_std = (const float*)d_in[2];
    const float* eps0      = (const float*)d_in[3];
    const float* noise     = (const float*)d_in[4];
    const float* enc_w1    = (const float*)d_in[5];
    const float* enc_b1    = (const float*)d_in[6];
    const float* enc_w2    = (const float*)d_in[7];
    const float* enc_b2    = (const float*)d_in[8];
    const float* qz0_w     = (const float*)d_in[9];
    const float* qz0_b     = (const float*)d_in[10];
    const float* f_w1      = (const float*)d_in[11];
    const float* f_b1      = (const float*)d_in[12];
    const float* f_w2      = (const float*)d_in[13];
    const float* f_b2      = (const float*)d_in[14];
    const float* h_w1      = (const float*)d_in[15];
    const float* h_b1      = (const float*)d_in[16];
    const float* h_w2      = (const float*)d_in[17];
    const float* h_b2      = (const float*)d_in[18];
    const float* proj_w    = (const float*)d_in[19];
    const float* proj_b    = (const float*)d_in[20];
    const float* pz0_mean  = (const float*)d_in[21];
    const float* pz0_logstd= (const float*)d_in[22];
    const float* gamma     = (const float*)d_in[23];

    bf16 *y1, *ctx, *xst, *zs, *hf, *hh, *wtb, *fctx;
    float *z, *q, *dkl8, *kl0, *partials;
    unsigned *flagA, *flagB;
    cudaGetSymbolAddress((void**)&y1, g_y1);
    cudaGetSymbolAddress((void**)&ctx, g_ctx);
    cudaGetSymbolAddress((void**)&xst, g_xst);
    cudaGetSymbolAddress((void**)&zs, g_zs);
    cudaGetSymbolAddress((void**)&z, g_z);
    cudaGetSymbolAddress((void**)&hf, g_hf);
    cudaGetSymbolAddress((void**)&hh, g_hh);
    cudaGetSymbolAddress((void**)&q, g_q);
    cudaGetSymbolAddress((void**)&fctx, g_fctx);
    cudaGetSymbolAddress((void**)&wtb, g_wtb);
    cudaGetSymbolAddress((void**)&dkl8, g_dkl8);
    cudaGetSymbolAddress((void**)&kl0, g_kl0);
    cudaGetSymbolAddress((void**)&partials, g_partials);
    cudaGetSymbolAddress((void**)&flagA, g_flagA);
    cudaGetSymbolAddress((void**)&flagB, g_flagB);

    cudaFuncSetAttribute(gemm_bf<128,1,1,0,0>, cudaFuncAttributeMaxDynamicSharedMemorySize, SMEM128);
    cudaFuncSetAttribute(gemm_bf<128,0,1,0,0>, cudaFuncAttributeMaxDynamicSharedMemorySize, SMEM128);
    cudaFuncSetAttribute(gemm_bf<128,0,0,0,0>, cudaFuncAttributeMaxDynamicSharedMemorySize, SMEM128);
    cudaFuncSetAttribute(gemm_bf<128,0,0,1,0>, cudaFuncAttributeMaxDynamicSharedMemorySize, SMEM128);
    cudaFuncSetAttribute(gemm_bf<128,0,0,0,1>, cudaFuncAttributeMaxDynamicSharedMemorySize, SMEM128);
    cudaFuncSetAttribute(scan_k, cudaFuncAttributeMaxDynamicSharedMemorySize, SMEMP);

    const int M = NB * NT;

    // ---- launch 1: fused prep ----
    {
        PrepArgs pa{};
        const float* srcs[9] = {enc_w1, enc_w2, qz0_w, f_w1, f_w1 + 256 * NH,
                                f_w2, h_w1, h_w2, proj_w};
        int offs[9] = {W_ENC1, W_ENC2, W_QZ0, W_F1Z, W_F1C, W_F2, W_H1, W_H2, W_PROJ};
        int Ks[9]   = {256, 1024, 512, 256, 512, 1024, 256, 1024, 256};
        int Ns[9]   = {1024, 256, 512, 1024, 1024, 256, 1024, 256, 256};
        int off = 0;
        for (int i = 0; i < 9; i++) {
            pa.src[i] = srcs[i]; pa.off[i] = offs[i]; pa.K[i] = Ks[i]; pa.N[i] = Ns[i];
            pa.tileOff[i] = off;
            off += (Ns[i] >> 5) * (Ks[i] >> 5);
        }
        pa.tileOff[9] = off;
        pa.xs = xs;
        const int nCopy = (int)((size_t)M * ND / 1024);
        prep_k<<<off + nCopy, 256>>>(pa, wtb, ctx, xst, dkl8, flagA, flagB);
    }

    GArgs zg{};

    // ---- encoder ----
    {
        GArgs a{xst, ND, wtb + W_ENC1, enc_b1, y1, NH, ND};
        gemm_bf<128,1,1,0,0><<<dim3(NH/128, M/128), 256, SMEM128>>>(a, a, M/128, nullptr, nullptr, nullptr);
    }
    {
        GArgs a{y1, NH, wtb + W_ENC2, enc_b2, ctx, 512, NH};
        gemm_bf<128,0,1,0,0><<<dim3(NL/128, M/128), 256, SMEM128>>>(a, a, M/128, nullptr, nullptr, nullptr);
    }

    // ---- fctx ----
    {
        GArgs a{ctx, 512, wtb + W_F1C, f_b1, fctx, NH, 512};
        gemm_bf<128,0,0,0,1><<<dim3(NH/128, M/128), 256, SMEM128>>>(a, a, M/128, nullptr, nullptr, nullptr);
    }

    // ---- q ----
    {
        GArgs a{ctx, NT * 512, wtb + W_QZ0, qz0_b, q, 512, 512};
        gemm_bf<128,0,0,0,0><<<dim3(512/128, NB/128), 256, SMEM128>>>(a, a, NB/128, nullptr, nullptr, nullptr);
    }

    // ---- persistent scan ----
    scan_k<<<128, 256, SMEMP>>>(ts, noise, z, zs, hf, hh,
                                wtb + W_F1Z, wtb + W_H1, wtb + W_F2, wtb + W_H2,
                                h_b1, f_b2, h_b2, fctx, gamma, dkl8, flagA, flagB,
                                q, eps0, pz0_mean, pz0_logstd, kl0);

    // ---- decoder fused with NLL reduction ----
    {
        GArgs a{zs, NL, wtb + W_PROJ, proj_b, nullptr, ND, NL};
        gemm_bf<128,0,0,1,0><<<dim3(ND/128, M/128), 256, SMEM128>>>(a, zg, M/128, xs, noise_std, partials);
    }

    // ---- finalize ----
    finalize_k<<<1, 256>>>(partials, (M/128) * (ND/128), dkl8, kl0, noise_std, (float*)d_out);

    (void)in_sizes; (void)n_in; (void)out_size;
}

// round 15
// speedup vs baseline: 1.1465x; 1.0698x over previous
#include <cuda_runtime.h>
#include <cuda_bf16.h>
#include <math.h>
#include <stdint.h>

// ---------------- problem dims ------------------------------------------------
#define NB 1024
#define NT 64
#define ND 256
#define NL 256
#define NH 1024
#define EPSV 1e-7f
#define LOG2PI 1.8378770664093453f
#define BETAV (1.0f/3.0f)

typedef __nv_bfloat16 bf16;

// ---------------- scratch (device globals) ------------------------------------
__device__ __align__(16) bf16  g_y1[(size_t)NB * NT * NH];
__device__ __align__(16) bf16  g_ctx[(size_t)NB * NT * 512];
__device__ __align__(16) bf16  g_xst[(size_t)NB * NT * ND];
__device__ __align__(16) bf16  g_zs[(size_t)NB * NT * NL];
__device__ __align__(16) float g_z[NB * NL];
__device__ __align__(16) bf16  g_hf[NB * NH];
__device__ __align__(16) bf16  g_hh[NB * NH];
__device__ __align__(16) float g_q[NB * 512];
__device__ __align__(16) bf16  g_fctx[(size_t)NT * NB * NH];   // [t][b][1024] bf16
__device__ __align__(16) bf16  g_wtb[2424832];
__device__ float g_dkl8[8 * NB];
__device__ float g_kl0[NB];
__device__ float g_partials[4096];
__device__ unsigned g_flagA[NT * 8];
__device__ unsigned g_flagB[NT * 8];   // slots 504..511 = z0-done

// weight offsets in g_wtb (elements), stored transposed [N][K]
#define W_ENC1 0
#define W_ENC2 262144
#define W_QZ0  524288
#define W_F1Z  786432
#define W_F1C  1048576
#define W_F2   1572864
#define W_H1   1835008
#define W_H2   2097152
#define W_PROJ 2359296

// ---------------- helpers -----------------------------------------------------
__device__ __forceinline__ uint32_t s2u(const void* p) {
    uint32_t a;
    asm("{ .reg .u64 t; cvta.to.shared.u64 t, %1; cvt.u32.u64 %0, t; }" : "=r"(a) : "l"(p));
    return a;
}
__device__ __forceinline__ void cp16(uint32_t saddr, const void* g) {
    asm volatile("cp.async.cg.shared.global [%0], [%1], 16;" :: "r"(saddr), "l"(g));
}
__device__ __forceinline__ void ldsm4(uint32_t& r0, uint32_t& r1, uint32_t& r2, uint32_t& r3,
                                      uint32_t addr) {
    asm volatile("ldmatrix.sync.aligned.m8n8.x4.shared.b16 {%0,%1,%2,%3}, [%4];"
                 : "=r"(r0), "=r"(r1), "=r"(r2), "=r"(r3) : "r"(addr));
}
__device__ __forceinline__ void mma_bf16(float* c, uint32_t a0, uint32_t a1, uint32_t a2, uint32_t a3,
                                         uint32_t b0, uint32_t b1) {
    asm volatile("mma.sync.aligned.m16n8k16.row.col.f32.bf16.bf16.f32 "
                 "{%0,%1,%2,%3},{%4,%5,%6,%7},{%8,%9},{%0,%1,%2,%3};"
                 : "+f"(c[0]), "+f"(c[1]), "+f"(c[2]), "+f"(c[3])
                 : "r"(a0), "r"(a1), "r"(a2), "r"(a3), "r"(b0), "r"(b1));
}
__device__ __forceinline__ float block_reduce_sum_256(float v, float* sh) {
    int tid = threadIdx.x;
    sh[tid] = v;
    __syncthreads();
    #pragma unroll
    for (int s = 128; s > 0; s >>= 1) {
        if (tid < s) sh[tid] += sh[tid + s];
        __syncthreads();
    }
    float r = sh[0];
    __syncthreads();
    return r;
}
__device__ __forceinline__ void wait_flag(unsigned* f, unsigned tgt) {
    if (threadIdx.x == 0) {
        unsigned v;
        do {
            asm volatile("ld.acquire.gpu.u32 %0, [%1];" : "=r"(v) : "l"(f) : "memory");
        } while (v < tgt);
    }
    __syncthreads();
}
__device__ __forceinline__ void arrive_flag(unsigned* f) {
    __syncthreads();
    if (threadIdx.x == 0)
        asm volatile("red.release.gpu.add.u32 [%0], 1;" :: "l"(f) : "memory");
}

// ldmatrix lane-offset builders (stride 72 bf16 rows, bytes)
// A (m16k16): row = lane&15, koff = (lane>>4)*8
__device__ __forceinline__ uint32_t laneA_off(int lane) {
    return (uint32_t)((((lane & 15) * 72) + (((lane >> 4) & 1) << 3)) << 1);
}
// B (two n8k16 groups): g=lane>>3; row = (lane&7) + (g>>1)*8, koff = (g&1)*8
__device__ __forceinline__ uint32_t laneB_off(int lane) {
    int g = lane >> 3;
    return (uint32_t)(((((lane & 7) + ((g >> 1) << 3)) * 72) + ((g & 1) << 3)) << 1);
}

// ---------------- standalone bf16 GEMM ----------------------------------------
struct GArgs {
    const bf16* A; int lda;
    const bf16* W;
    const float* bias;
    void* C; int ldc;
    int K;
};

template<int BMT, int ACT, int OUTBF, int EPI, int TSCAT>
__global__ void __launch_bounds__(256, 2)
gemm_bf(GArgs g0, GArgs g1, int mSplit,
        const float* __restrict__ xs, const float* __restrict__ nstd_p,
        float* __restrict__ partials)
{
    extern __shared__ char smem[];
    constexpr int MT  = (BMT + 31) / 32;
    constexpr int ASZ = BMT * 72;
    constexpr int BSZ = 128 * 72;
    constexpr int STG = ASZ + BSZ;

    const int tid  = threadIdx.x;
    const int wid  = tid >> 5;
    const int lane = tid & 31;
    const int lr   = lane >> 2;
    const int lc   = lane & 3;

    const bool grp1 = ((int)blockIdx.y >= mSplit);
    const GArgs g = grp1 ? g1 : g0;
    const int bm = (grp1 ? ((int)blockIdx.y - mSplit) : (int)blockIdx.y) * BMT;
    const int bn = (int)blockIdx.x * 128;

    const uint32_t sbase = s2u(smem);
    const int warpM = (wid >> 2) * (BMT / 2);
    const int warpN = (wid & 3) * 32;
    const uint32_t lA = laneA_off(lane);
    const uint32_t lB = laneB_off(lane);

    auto loadtile = [&](int s, int c) {
        const int k0 = c << 6;
        uint32_t sA = sbase + (uint32_t)(s * STG) * 2u;
        uint32_t sB = sA + (uint32_t)ASZ * 2u;
        const bf16* Ag = g.A + (size_t)bm * g.lda + k0;
        #pragma unroll
        for (int i = 0; i < BMT / 32; i++) {
            int idx = tid + (i << 8);
            int m = idx >> 3, k8 = (idx & 7) << 3;
            cp16(sA + (uint32_t)(m * 72 + k8) * 2u, Ag + (size_t)m * g.lda + k8);
        }
        const bf16* Wg = g.W + (size_t)bn * g.K + k0;
        #pragma unroll
        for (int i = 0; i < 4; i++) {
            int idx = tid + (i << 8);
            int n = idx >> 3, k8 = (idx & 7) << 3;
            cp16(sB + (uint32_t)(n * 72 + k8) * 2u, Wg + (size_t)n * g.K + k8);
        }
        asm volatile("cp.async.commit_group;" ::: "memory");
    };

    float acc[MT][4][4];
    #pragma unroll
    for (int mt = 0; mt < MT; mt++)
        #pragma unroll
        for (int nt = 0; nt < 4; nt++)
            #pragma unroll
            for (int r = 0; r < 4; r++) acc[mt][nt][r] = 0.f;

    const int nch = g.K >> 6;
    loadtile(0, 0);
    if (nch > 1) loadtile(1, 1);

    for (int c = 0; c < nch; c++) {
        if (c + 1 < nch) asm volatile("cp.async.wait_group 1;" ::: "memory");
        else             asm volatile("cp.async.wait_group 0;" ::: "memory");
        __syncthreads();
        const uint32_t stg = sbase + (uint32_t)((c & 1) * STG) * 2u;
        const uint32_t aB = stg + (uint32_t)(warpM * 144) + lA;
        const uint32_t bB = stg + (uint32_t)ASZ * 2u + (uint32_t)(warpN * 144) + lB;
        #pragma unroll
        for (int ks = 0; ks < 4; ks++) {
            uint32_t b0[4], b1[4];
            ldsm4(b0[0], b1[0], b0[1], b1[1], bB + ks * 32);
            ldsm4(b0[2], b1[2], b0[3], b1[3], bB + 16 * 144 + ks * 32);
            #pragma unroll
            for (int mt = 0; mt < MT; mt++) {
                uint32_t a0, a1, a2, a3;
                ldsm4(a0, a1, a2, a3, aB + (uint32_t)(mt * 16 * 144) + ks * 32);
                #pragma unroll
                for (int nt = 0; nt < 4; nt++)
                    mma_bf16(acc[mt][nt], a0, a1, a2, a3, b0[nt], b1[nt]);
            }
        }
        __syncthreads();
        if (c + 2 < nch) loadtile(c & 1, c + 2);
    }

    float loc = 0.f;
    const float invs = EPI ? (1.f / nstd_p[0]) : 0.f;
    #pragma unroll
    for (int mt = 0; mt < MT; mt++) {
        const int row0 = bm + warpM + mt * 16 + lr;
        #pragma unroll
        for (int nt = 0; nt < 4; nt++) {
            const int col = bn + warpN + nt * 8 + (lc << 1);
            float2 bb = *reinterpret_cast<const float2*>(g.bias + col);
            float v00 = acc[mt][nt][0] + bb.x;
            float v01 = acc[mt][nt][1] + bb.y;
            float v10 = acc[mt][nt][2] + bb.x;
            float v11 = acc[mt][nt][3] + bb.y;
            if (ACT) { v00 = tanhf(v00); v01 = tanhf(v01); v10 = tanhf(v10); v11 = tanhf(v11); }
            if (EPI) {
                float2 x0 = *reinterpret_cast<const float2*>(xs + (size_t)row0 * g.ldc + col);
                float2 x1 = *reinterpret_cast<const float2*>(xs + (size_t)(row0 + 8) * g.ldc + col);
                float r0 = (x0.x - v00) * invs, r1 = (x0.y - v01) * invs;
                float r2 = (x1.x - v10) * invs, r3 = (x1.y - v11) * invs;
                loc += r0 * r0 + r1 * r1 + r2 * r2 + r3 * r3;
            } else if (TSCAT) {
                bf16* Cb = (bf16*)g.C;
                size_t o0 = ((size_t)(row0 & 63) * NB + (row0 >> 6)) * NH + col;
                int row1 = row0 + 8;
                size_t o1 = ((size_t)(row1 & 63) * NB + (row1 >> 6)) * NH + col;
                *reinterpret_cast<__nv_bfloat162*>(Cb + o0) = __floats2bfloat162_rn(v00, v01);
                *reinterpret_cast<__nv_bfloat162*>(Cb + o1) = __floats2bfloat162_rn(v10, v11);
            } else if (OUTBF) {
                bf16* Cb = (bf16*)g.C;
                *reinterpret_cast<__nv_bfloat162*>(Cb + (size_t)row0 * g.ldc + col) = __floats2bfloat162_rn(v00, v01);
                *reinterpret_cast<__nv_bfloat162*>(Cb + (size_t)(row0 + 8) * g.ldc + col) = __floats2bfloat162_rn(v10, v11);
            } else {
                float* Cf = (float*)g.C;
                *reinterpret_cast<float2*>(Cf + (size_t)row0 * g.ldc + col) = make_float2(v00, v01);
                *reinterpret_cast<float2*>(Cf + (size_t)(row0 + 8) * g.ldc + col) = make_float2(v10, v11);
            }
        }
    }
    if (EPI) {
        __syncthreads();
        float tot = block_reduce_sum_256(loc, (float*)smem);
        if (tid == 0) partials[blockIdx.y * gridDim.x + blockIdx.x] = -0.5f * tot;
    }
}

// ---------------- fused prologue: transposes + xs copy + resets ----------------
struct PrepArgs {
    const float* src[9];
    int off[9];
    int K[9], N[9];
    int tileOff[10];
    const float* xs;
};

__global__ void __launch_bounds__(256)
prep_k(PrepArgs pa, bf16* __restrict__ wtb, bf16* __restrict__ ctx, bf16* __restrict__ xst,
       float* __restrict__ dkl8, unsigned* __restrict__ flagA, unsigned* __restrict__ flagB)
{
    __shared__ float t[32][33];
    const int bx = blockIdx.x;
    const int tid = threadIdx.x;

    if (bx == 0) {
        #pragma unroll
        for (int i = 0; i < 32; i++) dkl8[tid + i * 256] = 0.f;
        #pragma unroll
        for (int i = 0; i < 2; i++) {
            flagA[tid + i * 256] = 0u;
            flagB[tid + i * 256] = 0u;
        }
    }

    if (bx < pa.tileOff[9]) {
        int m = 0;
        #pragma unroll
        for (int i = 1; i < 9; i++) if (bx >= pa.tileOff[i]) m = i;
        const int local = bx - pa.tileOff[m];
        const int K = pa.K[m], N = pa.N[m];
        const int nTiles = N >> 5;
        const int n0 = (local % nTiles) << 5;
        const int k0 = (local / nTiles) << 5;
        const float* W = pa.src[m];
        bf16* Wt = wtb + pa.off[m];
        const int tx = tid & 31, ty = tid >> 5;
        #pragma unroll
        for (int j = 0; j < 4; j++)
            t[ty + j * 8][tx] = W[(size_t)(k0 + ty + j * 8) * N + n0 + tx];
        __syncthreads();
        #pragma unroll
        for (int j = 0; j < 4; j++)
            Wt[(size_t)(n0 + ty + j * 8) * K + k0 + tx] = __float2bfloat16(t[tx][ty + j * 8]);
    } else {
        size_t i0 = ((size_t)(bx - pa.tileOff[9]) << 10) + ((size_t)tid << 2);
        float4 v = *reinterpret_cast<const float4*>(pa.xs + i0);
        float vv[4] = {v.x, v.y, v.z, v.w};
        #pragma unroll
        for (int u = 0; u < 4; u++) {
            size_t idx = i0 + u;
            size_t bt = idx >> 8, d = idx & 255;
            bf16 b = __float2bfloat16(vv[u]);
            ctx[bt * 512 + 256 + d] = b;
            xst[idx] = b;
        }
    }
}

// ---------------- persistent scan ---------------------------------------------
__device__ void gemmA(const bf16* A, const bf16* W, bf16* C,
                      const bf16* fadd, const float* bias,
                      int bm, int bn, char* smem)
{
    constexpr int lda = NT * NL;
    constexpr int ASZ = 128 * 72, STG = 2 * 128 * 72;
    const int tid = threadIdx.x;
    const int wid = tid >> 5, lane = tid & 31;
    const int lr = lane >> 2, lc = lane & 3;
    const uint32_t sbase = s2u(smem);
    const int warpM = (wid >> 2) * 64;
    const int warpN = (wid & 3) * 32;
    const uint32_t lA = laneA_off(lane);
    const uint32_t lB = laneB_off(lane);

    auto loadtile = [&](int s, int c) {
        const int k0 = c << 6;
        uint32_t sA = sbase + (uint32_t)(s * STG) * 2u;
        uint32_t sB = sA + (uint32_t)ASZ * 2u;
        #pragma unroll
        for (int i = 0; i < 4; i++) {
            int idx = tid + (i << 8);
            int m = idx >> 3, k8 = (idx & 7) << 3;
            cp16(sA + (uint32_t)(m * 72 + k8) * 2u, A + (size_t)(bm + m) * lda + k0 + k8);
        }
        #pragma unroll
        for (int i = 0; i < 4; i++) {
            int idx = tid + (i << 8);
            int n = idx >> 3, k8 = (idx & 7) << 3;
            cp16(sB + (uint32_t)(n * 72 + k8) * 2u, W + (size_t)(bn + n) * 256 + k0 + k8);
        }
        asm volatile("cp.async.commit_group;" ::: "memory");
    };

    float acc[4][4][4];
    #pragma unroll
    for (int mt = 0; mt < 4; mt++)
        #pragma unroll
        for (int nt = 0; nt < 4; nt++)
            #pragma unroll
            for (int r = 0; r < 4; r++) acc[mt][nt][r] = 0.f;

    loadtile(0, 0);
    loadtile(1, 1);
    loadtile(2, 2);
    for (int c = 0; c < 4; c++) {
        if (c <= 1)      asm volatile("cp.async.wait_group 2;" ::: "memory");
        else if (c == 2) asm volatile("cp.async.wait_group 1;" ::: "memory");
        else             asm volatile("cp.async.wait_group 0;" ::: "memory");
        __syncthreads();
        if (c + 3 < 4) loadtile(c + 3, c + 3);

        const uint32_t stg = sbase + (uint32_t)(c * STG) * 2u;
        const uint32_t aB = stg + (uint32_t)(warpM * 144) + lA;
        const uint32_t bB = stg + (uint32_t)ASZ * 2u + (uint32_t)(warpN * 144) + lB;
        #pragma unroll
        for (int ks = 0; ks < 4; ks++) {
            uint32_t b0[4], b1[4];
            ldsm4(b0[0], b1[0], b0[1], b1[1], bB + ks * 32);
            ldsm4(b0[2], b1[2], b0[3], b1[3], bB + 16 * 144 + ks * 32);
            #pragma unroll
            for (int mt = 0; mt < 4; mt++) {
                uint32_t a0, a1, a2, a3;
                ldsm4(a0, a1, a2, a3, aB + (uint32_t)(mt * 16 * 144) + ks * 32);
                #pragma unroll
                for (int nt = 0; nt < 4; nt++)
                    mma_bf16(acc[mt][nt], a0, a1, a2, a3, b0[nt], b1[nt]);
            }
        }
    }

    #pragma unroll
    for (int mt = 0; mt < 4; mt++) {
        const int row0 = bm + warpM + mt * 16 + lr;
        #pragma unroll
        for (int nt = 0; nt < 4; nt++) {
            const int gcol = bn + warpN + nt * 8 + (lc << 1);
            float a00, a01, a10, a11;
            if (fadd) {
                __nv_bfloat162 f0 = *reinterpret_cast<const __nv_bfloat162*>(fadd + (size_t)row0 * NH + gcol);
                __nv_bfloat162 f1 = *reinterpret_cast<const __nv_bfloat162*>(fadd + (size_t)(row0 + 8) * NH + gcol);
                a00 = __low2float(f0); a01 = __high2float(f0);
                a10 = __low2float(f1); a11 = __high2float(f1);
            } else {
                float2 bb = *reinterpret_cast<const float2*>(bias + gcol);
                a00 = bb.x; a01 = bb.y; a10 = bb.x; a11 = bb.y;
            }
            float v00 = tanhf(acc[mt][nt][0] + a00);
            float v01 = tanhf(acc[mt][nt][1] + a01);
            float v10 = tanhf(acc[mt][nt][2] + a10);
            float v11 = tanhf(acc[mt][nt][3] + a11);
            *reinterpret_cast<__nv_bfloat162*>(C + (size_t)row0 * NH + gcol) = __floats2bfloat162_rn(v00, v01);
            *reinterpret_cast<__nv_bfloat162*>(C + (size_t)(row0 + 8) * NH + gcol) = __floats2bfloat162_rn(v10, v11);
        }
    }
}

#define SMEMP 147456

__global__ void __launch_bounds__(256)
scan_k(const float* __restrict__ ts, const float* __restrict__ noise,
       float* __restrict__ z, bf16* __restrict__ zs,
       bf16* __restrict__ hf, bf16* __restrict__ hh,
       const bf16* __restrict__ wf1z, const bf16* __restrict__ wh1,
       const bf16* __restrict__ wf2, const bf16* __restrict__ wh2,
       const float* __restrict__ hb1,
       const float* __restrict__ fb2, const float* __restrict__ hb2,
       const bf16* __restrict__ fctx,
       const float* __restrict__ gamma, float* __restrict__ dkl8,
       unsigned* flagA, unsigned* flagB,
       const float* __restrict__ q, const float* __restrict__ eps0,
       const float* __restrict__ pm, const float* __restrict__ pl,
       float* __restrict__ kl0)
{
    extern __shared__ char smem[];
    const int tid = threadIdx.x;
    const int cta = blockIdx.x;
    const int wid = tid >> 5, lane = tid & 31;
    const int lr = lane >> 2, lc = lane & 3;

    // ---- fused z0 prologue ----
    {
        const int b = cta * 8 + wid;
        float part = 0.f;
        #pragma unroll
        for (int j = 0; j < 8; j++) {
            const int l = lane + j * 32;
            float qm = q[b * 512 + l];
            float ql = q[b * 512 + 256 + l];
            float z0 = qm + expf(ql) * eps0[b * NL + l];
            z[b * NL + l] = z0;
            zs[(size_t)b * NT * NL + l] = __float2bfloat16(z0);
            float pmv = pm[l], plv = pl[l];
            float dm = qm - pmv;
            part += plv - ql + (expf(2.f * ql) + dm * dm) / (2.f * expf(2.f * plv)) - 0.5f;
        }
        #pragma unroll
        for (int s = 16; s > 0; s >>= 1) part += __shfl_xor_sync(0xffffffff, part, s);
        if (lane == 0) kl0[b] = part;
    }
    arrive_flag(&flagB[504 + (cta >> 4)]);

    const int a_bm = (cta >> 4) * 128;
    const int a_bnI = cta & 15;
    const int a_grp = a_bm >> 7;

    const int b_bm = (cta >> 3) * 64;
    const int b_ng = cta & 7;
    const int b_bn = b_ng * 32;
    const int b_grp = b_bm >> 7;

    constexpr int AF = 0, AH = 64 * 72, BF = 128 * 72, BH = 128 * 72 + 32 * 72;
    constexpr int STG2 = 192 * 72;
    const uint32_t sbase = s2u(smem);
    const uint32_t lA = laneA_off(lane);
    const uint32_t lB = laneB_off(lane);

    for (int t = 0; t < NT - 1; t++) {
        // ---------------- phase A ----------------
        wait_flag(&flagB[(t == 0) ? (504 + a_grp) : ((t - 1) * 8 + a_grp)], 16);

        const bf16* Az = zs + (size_t)t * NL;
        if (a_bnI < 8)
            gemmA(Az, wf1z, hf, fctx + (size_t)(t + 1) * NB * NH, nullptr,
                  a_bm, a_bnI * 128, smem);
        else
            gemmA(Az, wh1, hh, nullptr, hb1, a_bm, (a_bnI - 8) * 128, smem);

        arrive_flag(&flagA[t * 8 + a_grp]);

        // ---------------- phase B ----------------
        wait_flag(&flagA[t * 8 + b_grp], 16);

        auto loadB = [&](int s, int c) {
            const int k0 = c << 6;
            uint32_t base = sbase + (uint32_t)(s * STG2) * 2u;
            #pragma unroll
            for (int i = 0; i < 2; i++) {
                int idx = tid + (i << 8);
                int m = idx >> 3, k8 = (idx & 7) << 3;
                cp16(base + (uint32_t)(AF + m * 72 + k8) * 2u, hf + (size_t)(b_bm + m) * NH + k0 + k8);
                cp16(base + (uint32_t)(AH + m * 72 + k8) * 2u, hh + (size_t)(b_bm + m) * NH + k0 + k8);
            }
            {
                int n = tid >> 3, k8 = (tid & 7) << 3;
                cp16(base + (uint32_t)(BF + n * 72 + k8) * 2u, wf2 + (size_t)(b_bn + n) * NH + k0 + k8);
                cp16(base + (uint32_t)(BH + n * 72 + k8) * 2u, wh2 + (size_t)(b_bn + n) * NH + k0 + k8);
            }
            asm volatile("cp.async.commit_group;" ::: "memory");
        };

        float ad[2][4], ap_[2][4];
        #pragma unroll
        for (int nt = 0; nt < 2; nt++)
            #pragma unroll
            for (int r = 0; r < 4; r++) { ad[nt][r] = 0.f; ap_[nt][r] = 0.f; }

        const int warpM = (wid & 3) * 16;
        const int warpNl = (wid >> 2) * 16;
        loadB(0, 0);
        loadB(1, 1);
        loadB(2, 2);
        for (int c = 0; c < 16; c++) {
            if (c <= 13)      asm volatile("cp.async.wait_group 2;" ::: "memory");
            else if (c == 14) asm volatile("cp.async.wait_group 1;" ::: "memory");
            else              asm volatile("cp.async.wait_group 0;" ::: "memory");
            __syncthreads();
            if (c + 3 < 16) loadB((c + 3) & 3, c + 3);

            const uint32_t stb = sbase + (uint32_t)((c & 3) * STG2) * 2u;
            const uint32_t afB = stb + (uint32_t)(AF * 2 + warpM * 144) + lA;
            const uint32_t ahB = stb + (uint32_t)(AH * 2 + warpM * 144) + lA;
            const uint32_t bfB = stb + (uint32_t)(BF * 2 + warpNl * 144) + lB;
            const uint32_t bhB = stb + (uint32_t)(BH * 2 + warpNl * 144) + lB;
            #pragma unroll
            for (int ks = 0; ks < 4; ks++) {
                uint32_t fa0, fa1, fa2, fa3, ha0, ha1, ha2, ha3;
                ldsm4(fa0, fa1, fa2, fa3, afB + ks * 32);
                ldsm4(ha0, ha1, ha2, ha3, ahB + ks * 32);
                uint32_t fb0_[2], fb1_[2], hb0_[2], hb1_[2];
                ldsm4(fb0_[0], fb1_[0], fb0_[1], fb1_[1], bfB + ks * 32);
                ldsm4(hb0_[0], hb1_[0], hb0_[1], hb1_[1], bhB + ks * 32);
                #pragma unroll
                for (int nt = 0; nt < 2; nt++) {
                    mma_bf16(ad[nt],  fa0, fa1, fa2, fa3, fb0_[nt], fb1_[nt]);
                    mma_bf16(ap_[nt], ha0, ha1, ha2, ha3, hb0_[nt], hb1_[nt]);
                }
            }
        }

        // ---- fused step update ----
        const float dt = ts[t + 1] - ts[t];
        const float sq = sqrtf(dt);
        float* sred = (float*)smem;
        float pr_lo = 0.f, pr_hi = 0.f;

        #pragma unroll
        for (int nt = 0; nt < 2; nt++) {
            const int col = b_bn + warpNl + nt * 8 + (lc << 1);
            const float fb0 = fb2[col], fb1v = fb2[col + 1];
            const float hb0 = hb2[col], hb1v = hb2[col + 1];
            float d00 = ad[nt][0] + fb0, d01 = ad[nt][1] + fb1v;
            float d10 = ad[nt][2] + fb0, d11 = ad[nt][3] + fb1v;
            float p00 = ap_[nt][0] + hb0, p01 = ap_[nt][1] + hb1v;
            float p10 = ap_[nt][2] + hb0, p11 = ap_[nt][3] + hb1v;

            const float df0 = sqrtf(2.f / (BETAV * gamma[col]));
            const float df1 = sqrtf(2.f / (BETAV * gamma[col + 1]));
            float den0 = fabsf(df0) > EPSV ? df0 : ((df0 > 0.f) - (df0 < 0.f)) * EPSV;
            float den1 = fabsf(df1) > EPSV ? df1 : ((df1 > 0.f) - (df1 < 0.f)) * EPSV;
            float r00 = (d00 - p00) / den0, r01 = (d01 - p01) / den1;
            float r10 = (d10 - p10) / den0, r11 = (d11 - p11) / den1;
            pr_lo += r00 * r00 + r01 * r01;
            pr_hi += r10 * r10 + r11 * r11;

            const int b0r = b_bm + warpM + lr, b1r = b0r + 8;
            {
                size_t zi = (size_t)b0r * NL + col;
                float e0 = noise[((size_t)t * NB + b0r) * NL + col];
                float e1 = noise[((size_t)t * NB + b0r) * NL + col + 1];
                float zn0 = z[zi] + d00 * dt + df0 * sq * e0;
                float zn1 = z[zi + 1] + d01 * dt + df1 * sq * e1;
                z[zi] = zn0; z[zi + 1] = zn1;
                *reinterpret_cast<__nv_bfloat162*>(zs + ((size_t)b0r * NT + t + 1) * NL + col)
                    = __floats2bfloat162_rn(zn0, zn1);
            }
            {
                size_t zi = (size_t)b1r * NL + col;
                float e0 = noise[((size_t)t * NB + b1r) * NL + col];
                float e1 = noise[((size_t)t * NB + b1r) * NL + col + 1];
                float zn0 = z[zi] + d10 * dt + df0 * sq * e0;
                float zn1 = z[zi + 1] + d11 * dt + df1 * sq * e1;
                z[zi] = zn0; z[zi + 1] = zn1;
                *reinterpret_cast<__nv_bfloat162*>(zs + ((size_t)b1r * NT + t + 1) * NL + col)
                    = __floats2bfloat162_rn(zn0, zn1);
            }
        }

        pr_lo += __shfl_xor_sync(0xffffffff, pr_lo, 1);
        pr_lo += __shfl_xor_sync(0xffffffff, pr_lo, 2);
        pr_hi += __shfl_xor_sync(0xffffffff, pr_hi, 1);
        pr_hi += __shfl_xor_sync(0xffffffff, pr_hi, 2);
        const int ngrp = wid >> 2;
        __syncthreads();
        if (lc == 0) {
            sred[(warpM + lr) * 2 + ngrp] = pr_lo;
            sred[(warpM + lr + 8) * 2 + ngrp] = pr_hi;
        }
        __syncthreads();
        if (tid < 64)
            dkl8[b_ng * NB + b_bm + tid] += (sred[tid * 2] + sred[tid * 2 + 1]) * dt;

        arrive_flag(&flagB[t * 8 + b_grp]);
    }
}

// ---------------- finalize -----------------------------------------------------
__global__ void finalize_k(const float* __restrict__ partials, int np,
                           const float* __restrict__ dkl8, const float* __restrict__ kl0,
                           const float* __restrict__ nstd_p, float* __restrict__ out)
{
    __shared__ float sh[256];
    int tid = threadIdx.x;
    float s = 0.f;
    for (int i = tid; i < np; i += 256) s += partials[i];
    float tot = block_reduce_sum_256(s, sh);

    float s2 = 0.f;
    for (int i = tid; i < 8 * NB; i += 256) s2 += dkl8[i];
    float dkl_tot = block_reduce_sum_256(s2, sh);

    float s3 = 0.f;
    for (int i = tid; i < NB; i += 256) s3 += kl0[i];
    float kl0_tot = block_reduce_sum_256(s3, sh);

    if (tid == 0) {
        float nstd = nstd_p[0];
        float cst = (float)NT * (float)ND * (-logf(nstd) - 0.5f * LOG2PI);
        float log_pxs = tot / (float)NB + cst;
        out[0] = -log_pxs;
        out[1] = dkl_tot / (float)NB + kl0_tot / (float)NB;
    }
}

// ---------------- launch ------------------------------------------------------
#define SMEM128 (2 * (128*72 + 128*72) * 2)   // 73728

extern "C" void kernel_launch(void* const* d_in, const int* in_sizes, int n_in,
                              void* d_out, int out_size)
{
    const float* xs        = (const float*)d_in[0];
    const float* ts        = (const float*)d_in[1];
    const float* noise_std = (const float*)d_in[2];
    const float* eps0      = (const float*)d_in[3];
    const float* noise     = (const float*)d_in[4];
    const float* enc_w1    = (const float*)d_in[5];
    const float* enc_b1    = (const float*)d_in[6];
    const float* enc_w2    = (const float*)d_in[7];
    const float* enc_b2    = (const float*)d_in[8];
    const float* qz0_w     = (const float*)d_in[9];
    const float* qz0_b     = (const float*)d_in[10];
    const float* f_w1      = (const float*)d_in[11];
    const float* f_b1      = (const float*)d_in[12];
    const float* f_w2      = (const float*)d_in[13];
    const float* f_b2      = (const float*)d_in[14];
    const float* h_w1      = (const float*)d_in[15];
    const float* h_b1      = (const float*)d_in[16];
    const float* h_w2      = (const float*)d_in[17];
    const float* h_b2      = (const float*)d_in[18];
    const float* proj_w    = (const float*)d_in[19];
    const float* proj_b    = (const float*)d_in[20];
    const float* pz0_mean  = (const float*)d_in[21];
    const float* pz0_logstd= (const float*)d_in[22];
    const float* gamma     = (const float*)d_in[23];

    bf16 *y1, *ctx, *xst, *zs, *hf, *hh, *wtb, *fctx;
    float *z, *q, *dkl8, *kl0, *partials;
    unsigned *flagA, *flagB;
    cudaGetSymbolAddress((void**)&y1, g_y1);
    cudaGetSymbolAddress((void**)&ctx, g_ctx);
    cudaGetSymbolAddress((void**)&xst, g_xst);
    cudaGetSymbolAddress((void**)&zs, g_zs);
    cudaGetSymbolAddress((void**)&z, g_z);
    cudaGetSymbolAddress((void**)&hf, g_hf);
    cudaGetSymbolAddress((void**)&hh, g_hh);
    cudaGetSymbolAddress((void**)&q, g_q);
    cudaGetSymbolAddress((void**)&fctx, g_fctx);
    cudaGetSymbolAddress((void**)&wtb, g_wtb);
    cudaGetSymbolAddress((void**)&dkl8, g_dkl8);
    cudaGetSymbolAddress((void**)&kl0, g_kl0);
    cudaGetSymbolAddress((void**)&partials, g_partials);
    cudaGetSymbolAddress((void**)&flagA, g_flagA);
    cudaGetSymbolAddress((void**)&flagB, g_flagB);

    cudaFuncSetAttribute(gemm_bf<128,1,1,0,0>, cudaFuncAttributeMaxDynamicSharedMemorySize, SMEM128);
    cudaFuncSetAttribute(gemm_bf<128,0,1,0,0>, cudaFuncAttributeMaxDynamicSharedMemorySize, SMEM128);
    cudaFuncSetAttribute(gemm_bf<128,0,0,0,0>, cudaFuncAttributeMaxDynamicSharedMemorySize, SMEM128);
    cudaFuncSetAttribute(gemm_bf<128,0,0,1,0>, cudaFuncAttributeMaxDynamicSharedMemorySize, SMEM128);
    cudaFuncSetAttribute(gemm_bf<128,0,0,0,1>, cudaFuncAttributeMaxDynamicSharedMemorySize, SMEM128);
    cudaFuncSetAttribute(scan_k, cudaFuncAttributeMaxDynamicSharedMemorySize, SMEMP);

    const int M = NB * NT;

    // ---- launch 1: fused prep ----
    {
        PrepArgs pa{};
        const float* srcs[9] = {enc_w1, enc_w2, qz0_w, f_w1, f_w1 + 256 * NH,
                                f_w2, h_w1, h_w2, proj_w};
        int offs[9] = {W_ENC1, W_ENC2, W_QZ0, W_F1Z, W_F1C, W_F2, W_H1, W_H2, W_PROJ};
        int Ks[9]   = {256, 1024, 512, 256, 512, 1024, 256, 1024, 256};
        int Ns[9]   = {1024, 256, 512, 1024, 1024, 256, 1024, 256, 256};
        int off = 0;
        for (int i = 0; i < 9; i++) {
            pa.src[i] = srcs[i]; pa.off[i] = offs[i]; pa.K[i] = Ks[i]; pa.N[i] = Ns[i];
            pa.tileOff[i] = off;
            off += (Ns[i] >> 5) * (Ks[i] >> 5);
        }
        pa.tileOff[9] = off;
        pa.xs = xs;
        const int nCopy = (int)((size_t)M * ND / 1024);
        prep_k<<<off + nCopy, 256>>>(pa, wtb, ctx, xst, dkl8, flagA, flagB);
    }

    GArgs zg{};

    // ---- encoder ----
    {
        GArgs a{xst, ND, wtb + W_ENC1, enc_b1, y1, NH, ND};
        gemm_bf<128,1,1,0,0><<<dim3(NH/128, M/128), 256, SMEM128>>>(a, a, M/128, nullptr, nullptr, nullptr);
    }
    {
        GArgs a{y1, NH, wtb + W_ENC2, enc_b2, ctx, 512, NH};
        gemm_bf<128,0,1,0,0><<<dim3(NL/128, M/128), 256, SMEM128>>>(a, a, M/128, nullptr, nullptr, nullptr);
    }

    // ---- fctx ----
    {
        GArgs a{ctx, 512, wtb + W_F1C, f_b1, fctx, NH, 512};
        gemm_bf<128,0,0,0,1><<<dim3(NH/128, M/128), 256, SMEM128>>>(a, a, M/128, nullptr, nullptr, nullptr);
    }

    // ---- q ----
    {
        GArgs a{ctx, NT * 512, wtb + W_QZ0, qz0_b, q, 512, 512};
        gemm_bf<128,0,0,0,0><<<dim3(512/128, NB/128), 256, SMEM128>>>(a, a, NB/128, nullptr, nullptr, nullptr);
    }

    // ---- persistent scan ----
    scan_k<<<128, 256, SMEMP>>>(ts, noise, z, zs, hf, hh,
                                wtb + W_F1Z, wtb + W_H1, wtb + W_F2, wtb + W_H2,
                                h_b1, f_b2, h_b2, fctx, gamma, dkl8, flagA, flagB,
                                q, eps0, pz0_mean, pz0_logstd, kl0);

    // ---- decoder fused with NLL reduction ----
    {
        GArgs a{zs, NL, wtb + W_PROJ, proj_b, nullptr, ND, NL};
        gemm_bf<128,0,0,1,0><<<dim3(ND/128, M/128), 256, SMEM128>>>(a, zg, M/128, xs, noise_std, partials);
    }

    // ---- finalize ----
    finalize_k<<<1, 256>>>(partials, (M/128) * (ND/128), dkl8, kl0, noise_std, (float*)d_out);

    (void)in_sizes; (void)n_in; (void)out_size;
}